// round 3
// baseline (speedup 1.0000x reference)
#include <cuda_runtime.h>
#include <math.h>
#include <stdint.h>

#define BATCH 2
#define SEQ   2048
#define DIM   1024
#define HEADS 16
#define HDIM  64
#define ROWS  (BATCH * SEQ)      // 4096
#define QKVN  (3 * DIM)          // 3072
#define EPS   1e-5f
#define INV_SCALE 0.125f         // 1/sqrt(64)

// ---------------- scratch (__device__ globals: no allocation allowed) --------
__device__ float g_zn [ROWS * DIM];
__device__ float g_q  [ROWS * DIM];   // [B*H, N, HD]
__device__ float g_k  [ROWS * DIM];
__device__ float g_v  [ROWS * DIM];
__device__ float g_att[ROWS * DIM];   // attention out [4096,1024]

// ---------------- tf32 helpers ----------------
__device__ __forceinline__ uint32_t f2tf(float x) {
    uint32_t r;
    asm("cvt.rna.tf32.f32 %0, %1;" : "=r"(r) : "f"(x));
    return r;
}
__device__ __forceinline__ void cvt2(float x, uint32_t& h, uint32_t& l) {
    h = f2tf(x);
    l = f2tf(x - __uint_as_float(h));
}
// D += A(16x8) * B(8x8), tf32 in, fp32 accum
__device__ __forceinline__ void mma8(float* c, const uint32_t* a, uint32_t b0, uint32_t b1) {
    asm volatile(
        "mma.sync.aligned.m16n8k8.row.col.f32.tf32.tf32.f32 "
        "{%0,%1,%2,%3}, {%4,%5,%6,%7}, {%8,%9}, {%0,%1,%2,%3};"
        : "+f"(c[0]), "+f"(c[1]), "+f"(c[2]), "+f"(c[3])
        : "r"(a[0]), "r"(a[1]), "r"(a[2]), "r"(a[3]), "r"(b0), "r"(b1));
}

// ---------------- LayerNorm ----------------
__global__ __launch_bounds__(256) void ln_kernel(
    const float* __restrict__ z, const float* __restrict__ sc,
    const float* __restrict__ bi, float* __restrict__ out)
{
    int row = blockIdx.x;
    int t = threadIdx.x;
    const float4 v = ((const float4*)(z + row * DIM))[t];
    float s  = v.x + v.y + v.z + v.w;
    float s2 = v.x*v.x + v.y*v.y + v.z*v.z + v.w*v.w;

    __shared__ float ssum[8], ssum2[8], stats[2];
    #pragma unroll
    for (int off = 16; off > 0; off >>= 1) {
        s  += __shfl_down_sync(0xffffffffu, s,  off);
        s2 += __shfl_down_sync(0xffffffffu, s2, off);
    }
    int lane = t & 31, wid = t >> 5;
    if (lane == 0) { ssum[wid] = s; ssum2[wid] = s2; }
    __syncthreads();
    if (t == 0) {
        float a = 0.f, b = 0.f;
        #pragma unroll
        for (int i = 0; i < 8; i++) { a += ssum[i]; b += ssum2[i]; }
        float mu  = a * (1.0f / DIM);
        float var = b * (1.0f / DIM) - mu * mu;
        stats[0] = mu;
        stats[1] = rsqrtf(var + EPS);
    }
    __syncthreads();
    float mu = stats[0], rstd = stats[1];
    float4 s4 = ((const float4*)sc)[t];
    float4 b4 = ((const float4*)bi)[t];
    float4 r;
    r.x = (v.x - mu) * rstd * s4.x + b4.x;
    r.y = (v.y - mu) * rstd * s4.y + b4.y;
    r.z = (v.z - mu) * rstd * s4.z + b4.z;
    r.w = (v.w - mu) * rstd * s4.w + b4.w;
    ((float4*)(out + row * DIM))[t] = r;
}

// ---------------- tf32x3 GEMM: 128x128 tile, kstep 32, 8 warps (2x4) --------
// MODE 0: C = A@B, scatter into g_q/g_k/g_v.  MODE 1: C = A@B + bias + zres.
#define GA_PAD 36
#define GB_PAD 136
#define GEMM_SMEM_BYTES ((2 * 128 * GA_PAD + 2 * 32 * GB_PAD) * 4)

template<int MODE>
__global__ __launch_bounds__(256) void gemm_tf32(
    const float* __restrict__ A, const float* __restrict__ B,
    float* __restrict__ C, const float* __restrict__ zres,
    const float* __restrict__ bias, int M, int Ncols, int K)
{
    extern __shared__ uint32_t smg[];
    uint32_t* Ah = smg;
    uint32_t* Al = Ah + 128 * GA_PAD;
    uint32_t* Bh = Al + 128 * GA_PAD;
    uint32_t* Bl = Bh + 32 * GB_PAD;

    int tid = threadIdx.x;
    int wid = tid >> 5, lane = tid & 31;
    int wm = wid >> 2, wn = wid & 3;      // warp grid 2x4
    int g = lane >> 2, qd = lane & 3;
    int bm = blockIdx.y * 128, bn = blockIdx.x * 128;

    // per-thread load coordinates
    int aR0 = tid >> 3;             // row in tile for A (plus 32*i)
    int aC0 = (tid & 7) * 4;        // col offset in k-tile
    int bR0 = tid >> 3;             // k-row for B
    int bC0 = (tid & 7) * 16;       // col in tile (plus 4*i)

    float acc[4][4][4] = {};
    float4 aReg[4], bReg[4];

    // prologue: fetch first k-tile
    #pragma unroll
    for (int i = 0; i < 4; i++) {
        aReg[i] = *(const float4*)(A + (size_t)(bm + aR0 + 32*i) * K + aC0);
        bReg[i] = *(const float4*)(B + (size_t)(bR0) * Ncols + bn + bC0 + 4*i);
    }
    // convert + store
    #pragma unroll
    for (int i = 0; i < 4; i++) {
        int r = aR0 + 32*i;
        uint32_t h, l;
        cvt2(aReg[i].x, h, l); Ah[r*GA_PAD+aC0  ] = h; Al[r*GA_PAD+aC0  ] = l;
        cvt2(aReg[i].y, h, l); Ah[r*GA_PAD+aC0+1] = h; Al[r*GA_PAD+aC0+1] = l;
        cvt2(aReg[i].z, h, l); Ah[r*GA_PAD+aC0+2] = h; Al[r*GA_PAD+aC0+2] = l;
        cvt2(aReg[i].w, h, l); Ah[r*GA_PAD+aC0+3] = h; Al[r*GA_PAD+aC0+3] = l;
        int c = bC0 + 4*i;
        cvt2(bReg[i].x, h, l); Bh[bR0*GB_PAD+c  ] = h; Bl[bR0*GB_PAD+c  ] = l;
        cvt2(bReg[i].y, h, l); Bh[bR0*GB_PAD+c+1] = h; Bl[bR0*GB_PAD+c+1] = l;
        cvt2(bReg[i].z, h, l); Bh[bR0*GB_PAD+c+2] = h; Bl[bR0*GB_PAD+c+2] = l;
        cvt2(bReg[i].w, h, l); Bh[bR0*GB_PAD+c+3] = h; Bl[bR0*GB_PAD+c+3] = l;
    }
    __syncthreads();

    for (int kk = 0; kk < K; kk += 32) {
        bool more = (kk + 32) < K;
        // prefetch next k-tile into registers (overlaps with compute below)
        if (more) {
            #pragma unroll
            for (int i = 0; i < 4; i++) {
                aReg[i] = *(const float4*)(A + (size_t)(bm + aR0 + 32*i) * K + kk + 32 + aC0);
                bReg[i] = *(const float4*)(B + (size_t)(kk + 32 + bR0) * Ncols + bn + bC0 + 4*i);
            }
        }

        // compute current tile
        #pragma unroll
        for (int ks = 0; ks < 4; ks++) {
            int k8 = ks * 8;
            uint32_t ah[4][4], al_[4][4];
            #pragma unroll
            for (int mi = 0; mi < 4; mi++) {
                int base = (64*wm + 16*mi + g) * GA_PAD + k8 + qd;
                ah [mi][0] = Ah[base];              ah [mi][1] = Ah[base + 8*GA_PAD];
                ah [mi][2] = Ah[base + 4];          ah [mi][3] = Ah[base + 8*GA_PAD + 4];
                al_[mi][0] = Al[base];              al_[mi][1] = Al[base + 8*GA_PAD];
                al_[mi][2] = Al[base + 4];          al_[mi][3] = Al[base + 8*GA_PAD + 4];
            }
            uint32_t bh[4][2], bl[4][2];
            #pragma unroll
            for (int ni = 0; ni < 4; ni++) {
                int base = (k8 + qd) * GB_PAD + 32*wn + 8*ni + g;
                bh[ni][0] = Bh[base]; bh[ni][1] = Bh[base + 4*GB_PAD];
                bl[ni][0] = Bl[base]; bl[ni][1] = Bl[base + 4*GB_PAD];
            }
            // term passes: 16 independent MMAs per pass (no RAW chains)
            #pragma unroll
            for (int mi = 0; mi < 4; mi++)
                #pragma unroll
                for (int ni = 0; ni < 4; ni++)
                    mma8(acc[mi][ni], ah[mi], bh[ni][0], bh[ni][1]);
            #pragma unroll
            for (int mi = 0; mi < 4; mi++)
                #pragma unroll
                for (int ni = 0; ni < 4; ni++)
                    mma8(acc[mi][ni], al_[mi], bh[ni][0], bh[ni][1]);
            #pragma unroll
            for (int mi = 0; mi < 4; mi++)
                #pragma unroll
                for (int ni = 0; ni < 4; ni++)
                    mma8(acc[mi][ni], ah[mi], bl[ni][0], bl[ni][1]);
        }

        if (more) {
            __syncthreads();   // all readers done with current smem tile
            #pragma unroll
            for (int i = 0; i < 4; i++) {
                int r = aR0 + 32*i;
                uint32_t h, l;
                cvt2(aReg[i].x, h, l); Ah[r*GA_PAD+aC0  ] = h; Al[r*GA_PAD+aC0  ] = l;
                cvt2(aReg[i].y, h, l); Ah[r*GA_PAD+aC0+1] = h; Al[r*GA_PAD+aC0+1] = l;
                cvt2(aReg[i].z, h, l); Ah[r*GA_PAD+aC0+2] = h; Al[r*GA_PAD+aC0+2] = l;
                cvt2(aReg[i].w, h, l); Ah[r*GA_PAD+aC0+3] = h; Al[r*GA_PAD+aC0+3] = l;
                int c = bC0 + 4*i;
                cvt2(bReg[i].x, h, l); Bh[bR0*GB_PAD+c  ] = h; Bl[bR0*GB_PAD+c  ] = l;
                cvt2(bReg[i].y, h, l); Bh[bR0*GB_PAD+c+1] = h; Bl[bR0*GB_PAD+c+1] = l;
                cvt2(bReg[i].z, h, l); Bh[bR0*GB_PAD+c+2] = h; Bl[bR0*GB_PAD+c+2] = l;
                cvt2(bReg[i].w, h, l); Bh[bR0*GB_PAD+c+3] = h; Bl[bR0*GB_PAD+c+3] = l;
            }
            __syncthreads();
        }
    }

    // epilogue
    #pragma unroll
    for (int mi = 0; mi < 4; mi++)
        #pragma unroll
        for (int ni = 0; ni < 4; ni++)
            #pragma unroll
            for (int j = 0; j < 4; j++) {
                int gm = bm + 64*wm + 16*mi + g + ((j >> 1) << 3);
                int gn = bn + 32*wn + 8*ni + 2*qd + (j & 1);
                if (MODE == 0) {
                    int bb = gm >> 11;
                    int nn = gm & (SEQ - 1);
                    int h   = gn / 192;
                    int rem = gn - h * 192;
                    int d   = rem / 3;
                    int w   = rem - d * 3;
                    float* dst = (w == 0) ? g_q : (w == 1) ? g_k : g_v;
                    dst[(((size_t)bb * HEADS + h) * SEQ + nn) * HDIM + d] = acc[mi][ni][j];
                } else {
                    size_t idx = (size_t)gm * Ncols + gn;
                    C[idx] = acc[mi][ni][j] + bias[gn] + zres[idx];
                }
            }
}

// ---------------- tf32x3 flash attention ----------------
// block = 256 thr (8 warps), tile: 128 q-rows x 64 k-cols, HD=64.
// warp w owns q-rows [16w, 16w+16).
#define QP 68
#define KP 72
#define ATTN_SMEM_BYTES ((2*128*QP + 4*64*KP + 2*128*QP) * 4)   // 212992

__global__ __launch_bounds__(256) void attn_tf32(float* __restrict__ Out)
{
    extern __shared__ uint32_t sma[];
    uint32_t* Qh = sma;
    uint32_t* Ql = Qh + 128 * QP;
    uint32_t* Kh = Ql + 128 * QP;
    uint32_t* Kl = Kh + 64 * KP;
    uint32_t* Vh = Kl + 64 * KP;
    uint32_t* Vl = Vh + 64 * KP;
    uint32_t* Ph = Vl + 64 * KP;
    uint32_t* Pl = Ph + 128 * QP;

    int tid = threadIdx.x;
    int wid = tid >> 5, lane = tid & 31;
    int g = lane >> 2, qd = lane & 3;
    int bh = blockIdx.y;
    int q0 = blockIdx.x * 128;
    int mrow = wid * 16;

    const float* Qb = g_q + ((size_t)bh * SEQ + q0) * HDIM;
    #pragma unroll
    for (int j = 0; j < 8; j++) {
        int idx = tid + 256 * j;
        int r = idx >> 4, c = (idx & 15) * 4;
        float4 v = *(const float4*)(Qb + r * 64 + c);
        uint32_t h, l;
        cvt2(v.x, h, l); Qh[r*QP+c  ] = h; Ql[r*QP+c  ] = l;
        cvt2(v.y, h, l); Qh[r*QP+c+1] = h; Ql[r*QP+c+1] = l;
        cvt2(v.z, h, l); Qh[r*QP+c+2] = h; Ql[r*QP+c+2] = l;
        cvt2(v.w, h, l); Qh[r*QP+c+3] = h; Ql[r*QP+c+3] = l;
    }

    float o[8][4] = {};
    float m0 = -1e30f, m1 = -1e30f, l0 = 0.f, l1 = 0.f;

    // K/V prefetch registers
    float4 kReg[4], vReg[4];
    {
        const float* Kb = g_k + (size_t)bh * SEQ * HDIM;
        const float* Vb = g_v + (size_t)bh * SEQ * HDIM;
        #pragma unroll
        for (int j = 0; j < 4; j++) {
            int idx = tid + 256 * j;
            int r = idx >> 4, c = (idx & 15) * 4;
            kReg[j] = *(const float4*)(Kb + r * 64 + c);
            vReg[j] = *(const float4*)(Vb + r * 64 + c);
        }
    }

    for (int kt = 0; kt < SEQ / 64; kt++) {
        __syncthreads();   // previous iteration's K/V/P readers done

        // store prefetched K/V tile (convert hi/lo)
        #pragma unroll
        for (int j = 0; j < 4; j++) {
            int idx = tid + 256 * j;
            int r = idx >> 4, c = (idx & 15) * 4;
            uint32_t h, l;
            cvt2(kReg[j].x, h, l); Kh[r*KP+c  ] = h; Kl[r*KP+c  ] = l;
            cvt2(kReg[j].y, h, l); Kh[r*KP+c+1] = h; Kl[r*KP+c+1] = l;
            cvt2(kReg[j].z, h, l); Kh[r*KP+c+2] = h; Kl[r*KP+c+2] = l;
            cvt2(kReg[j].w, h, l); Kh[r*KP+c+3] = h; Kl[r*KP+c+3] = l;
            cvt2(vReg[j].x, h, l); Vh[r*KP+c  ] = h; Vl[r*KP+c  ] = l;
            cvt2(vReg[j].y, h, l); Vh[r*KP+c+1] = h; Vl[r*KP+c+1] = l;
            cvt2(vReg[j].z, h, l); Vh[r*KP+c+2] = h; Vl[r*KP+c+2] = l;
            cvt2(vReg[j].w, h, l); Vh[r*KP+c+3] = h; Vl[r*KP+c+3] = l;
        }
        __syncthreads();

        // prefetch next K/V tile (overlaps QK + softmax + PV)
        if (kt + 1 < SEQ / 64) {
            const float* Kb = g_k + ((size_t)bh * SEQ + (kt + 1) * 64) * HDIM;
            const float* Vb = g_v + ((size_t)bh * SEQ + (kt + 1) * 64) * HDIM;
            #pragma unroll
            for (int j = 0; j < 4; j++) {
                int idx = tid + 256 * j;
                int r = idx >> 4, c = (idx & 15) * 4;
                kReg[j] = *(const float4*)(Kb + r * 64 + c);
                vReg[j] = *(const float4*)(Vb + r * 64 + c);
            }
        }

        // S = Q @ K^T  (16 x 64 per warp)
        float s[8][4] = {};
        #pragma unroll
        for (int k8 = 0; k8 < 64; k8 += 8) {
            uint32_t ah[4], al_[4];
            int abase = (mrow + g) * QP + k8 + qd;
            ah [0] = Qh[abase];          ah [1] = Qh[abase + 8*QP];
            ah [2] = Qh[abase + 4];      ah [3] = Qh[abase + 8*QP + 4];
            al_[0] = Ql[abase];          al_[1] = Ql[abase + 8*QP];
            al_[2] = Ql[abase + 4];      al_[3] = Ql[abase + 8*QP + 4];
            uint32_t bh_[8][2], bl_[8][2];
            #pragma unroll
            for (int ni = 0; ni < 8; ni++) {
                int bbase = (8*ni + g) * KP + k8 + qd;
                bh_[ni][0] = Kh[bbase]; bh_[ni][1] = Kh[bbase + 4];
                bl_[ni][0] = Kl[bbase]; bl_[ni][1] = Kl[bbase + 4];
            }
            #pragma unroll
            for (int ni = 0; ni < 8; ni++) mma8(s[ni], ah,  bh_[ni][0], bh_[ni][1]);
            #pragma unroll
            for (int ni = 0; ni < 8; ni++) mma8(s[ni], al_, bh_[ni][0], bh_[ni][1]);
            #pragma unroll
            for (int ni = 0; ni < 8; ni++) mma8(s[ni], ah,  bl_[ni][0], bl_[ni][1]);
        }
        #pragma unroll
        for (int ni = 0; ni < 8; ni++)
            #pragma unroll
            for (int j = 0; j < 4; j++) s[ni][j] *= INV_SCALE;

        // online softmax (rows g and g+8 of this warp's 16)
        float t0 = -1e30f, t1 = -1e30f;
        #pragma unroll
        for (int ni = 0; ni < 8; ni++) {
            t0 = fmaxf(t0, fmaxf(s[ni][0], s[ni][1]));
            t1 = fmaxf(t1, fmaxf(s[ni][2], s[ni][3]));
        }
        t0 = fmaxf(t0, __shfl_xor_sync(0xffffffffu, t0, 1));
        t0 = fmaxf(t0, __shfl_xor_sync(0xffffffffu, t0, 2));
        t1 = fmaxf(t1, __shfl_xor_sync(0xffffffffu, t1, 1));
        t1 = fmaxf(t1, __shfl_xor_sync(0xffffffffu, t1, 2));
        float mn0 = fmaxf(m0, t0), mn1 = fmaxf(m1, t1);
        float a0 = __expf(m0 - mn0), a1 = __expf(m1 - mn1);
        m0 = mn0; m1 = mn1;
        float p0 = 0.f, p1 = 0.f;
        #pragma unroll
        for (int ni = 0; ni < 8; ni++) {
            s[ni][0] = __expf(s[ni][0] - mn0); p0 += s[ni][0];
            s[ni][1] = __expf(s[ni][1] - mn0); p0 += s[ni][1];
            s[ni][2] = __expf(s[ni][2] - mn1); p1 += s[ni][2];
            s[ni][3] = __expf(s[ni][3] - mn1); p1 += s[ni][3];
        }
        p0 += __shfl_xor_sync(0xffffffffu, p0, 1);
        p0 += __shfl_xor_sync(0xffffffffu, p0, 2);
        p1 += __shfl_xor_sync(0xffffffffu, p1, 1);
        p1 += __shfl_xor_sync(0xffffffffu, p1, 2);
        l0 = l0 * a0 + p0;
        l1 = l1 * a1 + p1;
        #pragma unroll
        for (int ni = 0; ni < 8; ni++) {
            o[ni][0] *= a0; o[ni][1] *= a0;
            o[ni][2] *= a1; o[ni][3] *= a1;
        }

        // write P (hi/lo) to smem for PV A-fragments
        #pragma unroll
        for (int ni = 0; ni < 8; ni++) {
            int r0 = mrow + g;
            int col = 8*ni + 2*qd;
            uint32_t h, l;
            cvt2(s[ni][0], h, l); Ph[r0*QP + col    ] = h; Pl[r0*QP + col    ] = l;
            cvt2(s[ni][1], h, l); Ph[r0*QP + col + 1] = h; Pl[r0*QP + col + 1] = l;
            cvt2(s[ni][2], h, l); Ph[(r0+8)*QP + col    ] = h; Pl[(r0+8)*QP + col    ] = l;
            cvt2(s[ni][3], h, l); Ph[(r0+8)*QP + col + 1] = h; Pl[(r0+8)*QP + col + 1] = l;
        }
        __syncthreads();

        // O += P @ V
        #pragma unroll
        for (int k8 = 0; k8 < 64; k8 += 8) {
            uint32_t ah[4], al_[4];
            int abase = (mrow + g) * QP + k8 + qd;
            ah [0] = Ph[abase];          ah [1] = Ph[abase + 8*QP];
            ah [2] = Ph[abase + 4];      ah [3] = Ph[abase + 8*QP + 4];
            al_[0] = Pl[abase];          al_[1] = Pl[abase + 8*QP];
            al_[2] = Pl[abase + 4];      al_[3] = Pl[abase + 8*QP + 4];
            uint32_t bh_[8][2], bl_[8][2];
            #pragma unroll
            for (int ni = 0; ni < 8; ni++) {
                int bbase = (k8 + qd) * KP + 8*ni + g;
                bh_[ni][0] = Vh[bbase]; bh_[ni][1] = Vh[bbase + 4*KP];
                bl_[ni][0] = Vl[bbase]; bl_[ni][1] = Vl[bbase + 4*KP];
            }
            #pragma unroll
            for (int ni = 0; ni < 8; ni++) mma8(o[ni], ah,  bh_[ni][0], bh_[ni][1]);
            #pragma unroll
            for (int ni = 0; ni < 8; ni++) mma8(o[ni], al_, bh_[ni][0], bh_[ni][1]);
            #pragma unroll
            for (int ni = 0; ni < 8; ni++) mma8(o[ni], ah,  bl_[ni][0], bl_[ni][1]);
        }
    }

    // final: divide by l, write merged-head layout
    float inv0 = 1.f / l0, inv1 = 1.f / l1;
    int b = bh >> 4, h = bh & 15;
    int n0 = q0 + mrow + g;
    #pragma unroll
    for (int ni = 0; ni < 8; ni++) {
        int col = h * HDIM + 8*ni + 2*qd;
        Out[((size_t)b * SEQ + n0) * DIM + col    ] = o[ni][0] * inv0;
        Out[((size_t)b * SEQ + n0) * DIM + col + 1] = o[ni][1] * inv0;
        Out[((size_t)b * SEQ + n0 + 8) * DIM + col    ] = o[ni][2] * inv1;
        Out[((size_t)b * SEQ + n0 + 8) * DIM + col + 1] = o[ni][3] * inv1;
    }
}

// ---------------- launch ----------------
extern "C" void kernel_launch(void* const* d_in, const int* in_sizes, int n_in,
                              void* d_out, int out_size)
{
    const float* z        = (const float*)d_in[0];
    const float* ln_scale = (const float*)d_in[1];
    const float* ln_bias  = (const float*)d_in[2];
    const float* w_qkv    = (const float*)d_in[3];
    const float* w_proj   = (const float*)d_in[4];
    const float* b_proj   = (const float*)d_in[5];
    float* out = (float*)d_out;

    float *zn, *att;
    cudaGetSymbolAddress((void**)&zn,  g_zn);
    cudaGetSymbolAddress((void**)&att, g_att);

    cudaFuncSetAttribute(gemm_tf32<0>, cudaFuncAttributeMaxDynamicSharedMemorySize, GEMM_SMEM_BYTES);
    cudaFuncSetAttribute(gemm_tf32<1>, cudaFuncAttributeMaxDynamicSharedMemorySize, GEMM_SMEM_BYTES);
    cudaFuncSetAttribute(attn_tf32,    cudaFuncAttributeMaxDynamicSharedMemorySize, ATTN_SMEM_BYTES);

    // 1) LayerNorm
    ln_kernel<<<ROWS, 256>>>(z, ln_scale, ln_bias, zn);

    // 2) QKV GEMM with de-interleave scatter epilogue
    gemm_tf32<0><<<dim3(QKVN / 128, ROWS / 128), 256, GEMM_SMEM_BYTES>>>(
        zn, w_qkv, nullptr, nullptr, nullptr, ROWS, QKVN, DIM);

    // 3) attention (tf32x3 flash)
    attn_tf32<<<dim3(SEQ / 128, BATCH * HEADS), 256, ATTN_SMEM_BYTES>>>(att);

    // 4) output projection + bias + residual
    gemm_tf32<1><<<dim3(DIM / 128, ROWS / 128), 256, GEMM_SMEM_BYTES>>>(
        att, w_proj, out, z, b_proj, ROWS, DIM, DIM);
}

// round 4
// speedup vs baseline: 1.9860x; 1.9860x over previous
#include <cuda_runtime.h>
#include <cuda_bf16.h>
#include <math.h>
#include <stdint.h>

#define BATCH 2
#define SEQ   2048
#define DIM   1024
#define HEADS 16
#define HDIM  64
#define ROWS  (BATCH * SEQ)      // 4096
#define QKVN  (3 * DIM)          // 3072
#define EPS   1e-5f
#define INV_SCALE 0.125f         // 1/sqrt(64)

// ---------------- scratch (__device__ globals: no allocation allowed) --------
__device__ float g_zn [ROWS * DIM];
__device__ float g_q  [ROWS * DIM];   // [B*H, N, HD]
__device__ float g_k  [ROWS * DIM];
__device__ float g_v  [ROWS * DIM];
__device__ float g_att[ROWS * DIM];   // attention out [4096,1024]

// ---------------- bf16 split helpers ----------------
// split two floats into packed bf16x2 (hi) and packed bf16x2 (lo residual)
__device__ __forceinline__ void split2(float x, float y, uint32_t& h, uint32_t& l) {
    __nv_bfloat16 hx = __float2bfloat16(x);
    __nv_bfloat16 hy = __float2bfloat16(y);
    __nv_bfloat16 lx = __float2bfloat16(x - __bfloat162float(hx));
    __nv_bfloat16 ly = __float2bfloat16(y - __bfloat162float(hy));
    __nv_bfloat162 hh; hh.x = hx; hh.y = hy;
    __nv_bfloat162 ll; ll.x = lx; ll.y = ly;
    h = *reinterpret_cast<uint32_t*>(&hh);
    l = *reinterpret_cast<uint32_t*>(&ll);
}
// D += A(16x16) * B(16x8), bf16 in, fp32 accum
__device__ __forceinline__ void mma16(float* c, const uint32_t* a, uint32_t b0, uint32_t b1) {
    asm volatile(
        "mma.sync.aligned.m16n8k16.row.col.f32.bf16.bf16.f32 "
        "{%0,%1,%2,%3}, {%4,%5,%6,%7}, {%8,%9}, {%0,%1,%2,%3};"
        : "+f"(c[0]), "+f"(c[1]), "+f"(c[2]), "+f"(c[3])
        : "r"(a[0]), "r"(a[1]), "r"(a[2]), "r"(a[3]), "r"(b0), "r"(b1));
}

// ---------------- LayerNorm ----------------
__global__ __launch_bounds__(256) void ln_kernel(
    const float* __restrict__ z, const float* __restrict__ sc,
    const float* __restrict__ bi, float* __restrict__ out)
{
    int row = blockIdx.x;
    int t = threadIdx.x;
    const float4 v = ((const float4*)(z + row * DIM))[t];
    float s  = v.x + v.y + v.z + v.w;
    float s2 = v.x*v.x + v.y*v.y + v.z*v.z + v.w*v.w;

    __shared__ float ssum[8], ssum2[8], stats[2];
    #pragma unroll
    for (int off = 16; off > 0; off >>= 1) {
        s  += __shfl_down_sync(0xffffffffu, s,  off);
        s2 += __shfl_down_sync(0xffffffffu, s2, off);
    }
    int lane = t & 31, wid = t >> 5;
    if (lane == 0) { ssum[wid] = s; ssum2[wid] = s2; }
    __syncthreads();
    if (t == 0) {
        float a = 0.f, b = 0.f;
        #pragma unroll
        for (int i = 0; i < 8; i++) { a += ssum[i]; b += ssum2[i]; }
        float mu  = a * (1.0f / DIM);
        float var = b * (1.0f / DIM) - mu * mu;
        stats[0] = mu;
        stats[1] = rsqrtf(var + EPS);
    }
    __syncthreads();
    float mu = stats[0], rstd = stats[1];
    float4 s4 = ((const float4*)sc)[t];
    float4 b4 = ((const float4*)bi)[t];
    float4 r;
    r.x = (v.x - mu) * rstd * s4.x + b4.x;
    r.y = (v.y - mu) * rstd * s4.y + b4.y;
    r.z = (v.z - mu) * rstd * s4.z + b4.z;
    r.w = (v.w - mu) * rstd * s4.w + b4.w;
    ((float4*)(out + row * DIM))[t] = r;
}

// ---------------- bf16x3 GEMM: 128x128 tile, k-step 32, 8 warps (2x4) -------
// A smem: [128 rows][16 uint k-pairs], B smem transposed: [128 n][16 uint k-pairs]
#define AP 36
#define BP 37
#define GEMM_SMEM_BYTES ((2 * 128 * AP + 2 * 128 * BP) * 4)

template<int MODE>
__global__ __launch_bounds__(256) void gemm_bf16(
    const float* __restrict__ A, const float* __restrict__ B,
    float* __restrict__ C, const float* __restrict__ zres,
    const float* __restrict__ bias, int M, int Ncols, int K)
{
    extern __shared__ uint32_t smg[];
    uint32_t* Ah  = smg;
    uint32_t* Al  = Ah  + 128 * AP;
    uint32_t* Bth = Al  + 128 * AP;
    uint32_t* Btl = Bth + 128 * BP;

    int tid = threadIdx.x;
    int wid = tid >> 5, lane = tid & 31;
    int wm = wid >> 2, wn = wid & 3;       // 2x4 warp grid
    int g = lane >> 2, qd = lane & 3;
    int bm = blockIdx.y * 128, bn = blockIdx.x * 128;

    int aR0 = tid >> 3;                    // A row (+32*i)
    int aC0 = (tid & 7) * 4;               // A col in k-tile (even)
    int bP0 = tid >> 5;                    // B k-pair (+8*i)
    int bC0 = (tid & 31) * 4;              // B n-col

    float acc[4][4][4] = {};
    float4 aReg[4], bReg[2][2];

    // -- prologue fetch --
    #pragma unroll
    for (int i = 0; i < 4; i++)
        aReg[i] = *(const float4*)(A + (size_t)(bm + aR0 + 32*i) * K + aC0);
    #pragma unroll
    for (int i = 0; i < 2; i++)
        #pragma unroll
        for (int r = 0; r < 2; r++)
            bReg[i][r] = *(const float4*)(B + (size_t)(2*(bP0 + 8*i) + r) * Ncols + bn + bC0);

    // convert + store helper (macro-ish via lambda)
    auto storeAB = [&]() {
        #pragma unroll
        for (int i = 0; i < 4; i++) {
            int r = aR0 + 32*i;
            int cb = aC0 >> 1;
            uint32_t h, l;
            split2(aReg[i].x, aReg[i].y, h, l); Ah[r*AP+cb  ] = h; Al[r*AP+cb  ] = l;
            split2(aReg[i].z, aReg[i].w, h, l); Ah[r*AP+cb+1] = h; Al[r*AP+cb+1] = l;
        }
        #pragma unroll
        for (int i = 0; i < 2; i++) {
            int p = bP0 + 8*i;
            const float* r0 = (const float*)&bReg[i][0];
            const float* r1 = (const float*)&bReg[i][1];
            #pragma unroll
            for (int j = 0; j < 4; j++) {
                uint32_t h, l;
                split2(r0[j], r1[j], h, l);
                Bth[(bC0 + j)*BP + p] = h;
                Btl[(bC0 + j)*BP + p] = l;
            }
        }
    };

    storeAB();
    __syncthreads();

    for (int kk = 0; kk < K; kk += 32) {
        bool more = (kk + 32) < K;
        if (more) {
            #pragma unroll
            for (int i = 0; i < 4; i++)
                aReg[i] = *(const float4*)(A + (size_t)(bm + aR0 + 32*i) * K + kk + 32 + aC0);
            #pragma unroll
            for (int i = 0; i < 2; i++)
                #pragma unroll
                for (int r = 0; r < 2; r++)
                    bReg[i][r] = *(const float4*)(B + (size_t)(kk + 32 + 2*(bP0 + 8*i) + r) * Ncols + bn + bC0);
        }

        #pragma unroll
        for (int chunk = 0; chunk < 2; chunk++) {
            int u0 = 8 * chunk;
            uint32_t ah[4][4], al_[4][4];
            #pragma unroll
            for (int mi = 0; mi < 4; mi++) {
                int base = (64*wm + 16*mi + g) * AP + u0 + qd;
                ah [mi][0] = Ah[base];          ah [mi][1] = Ah[base + 8*AP];
                ah [mi][2] = Ah[base + 4];      ah [mi][3] = Ah[base + 8*AP + 4];
                al_[mi][0] = Al[base];          al_[mi][1] = Al[base + 8*AP];
                al_[mi][2] = Al[base + 4];      al_[mi][3] = Al[base + 8*AP + 4];
            }
            uint32_t bh[4][2], bl[4][2];
            #pragma unroll
            for (int ni = 0; ni < 4; ni++) {
                int base = (32*wn + 8*ni + g) * BP + u0 + qd;
                bh[ni][0] = Bth[base]; bh[ni][1] = Bth[base + 4];
                bl[ni][0] = Btl[base]; bl[ni][1] = Btl[base + 4];
            }
            // 3 term passes, 16 independent accumulators each
            #pragma unroll
            for (int mi = 0; mi < 4; mi++)
                #pragma unroll
                for (int ni = 0; ni < 4; ni++)
                    mma16(acc[mi][ni], ah[mi], bh[ni][0], bh[ni][1]);
            #pragma unroll
            for (int mi = 0; mi < 4; mi++)
                #pragma unroll
                for (int ni = 0; ni < 4; ni++)
                    mma16(acc[mi][ni], al_[mi], bh[ni][0], bh[ni][1]);
            #pragma unroll
            for (int mi = 0; mi < 4; mi++)
                #pragma unroll
                for (int ni = 0; ni < 4; ni++)
                    mma16(acc[mi][ni], ah[mi], bl[ni][0], bl[ni][1]);
        }

        if (more) {
            __syncthreads();
            storeAB();
            __syncthreads();
        }
    }

    // epilogue (C fragment layout identical to tf32 version)
    #pragma unroll
    for (int mi = 0; mi < 4; mi++)
        #pragma unroll
        for (int ni = 0; ni < 4; ni++)
            #pragma unroll
            for (int j = 0; j < 4; j++) {
                int gm = bm + 64*wm + 16*mi + g + ((j >> 1) << 3);
                int gn = bn + 32*wn + 8*ni + 2*qd + (j & 1);
                if (MODE == 0) {
                    int bb = gm >> 11;
                    int nn = gm & (SEQ - 1);
                    int h   = gn / 192;
                    int rem = gn - h * 192;
                    int d   = rem / 3;
                    int w   = rem - d * 3;
                    float* dst = (w == 0) ? g_q : (w == 1) ? g_k : g_v;
                    dst[(((size_t)bb * HEADS + h) * SEQ + nn) * HDIM + d] = acc[mi][ni][j];
                } else {
                    size_t idx = (size_t)gm * Ncols + gn;
                    C[idx] = acc[mi][ni][j] + bias[gn] + zres[idx];
                }
            }
}

// ---------------- bf16x3 flash attention, P kept in registers ----------------
// 256 thr (8 warps), tile 128 q x 64 kv, HD=64. Warp w owns q rows [16w,16w+16).
#define QP 36
#define KP 36
#define VP 35
#define ATTN_SMEM_BYTES ((2*128*QP + 2*64*KP + 2*64*VP) * 4)

__global__ __launch_bounds__(256) void attn_bf16(float* __restrict__ Out)
{
    extern __shared__ uint32_t sma[];
    uint32_t* Qh  = sma;
    uint32_t* Ql  = Qh  + 128 * QP;
    uint32_t* Kh  = Ql  + 128 * QP;
    uint32_t* Kl  = Kh  + 64 * KP;
    uint32_t* Vth = Kl  + 64 * KP;
    uint32_t* Vtl = Vth + 64 * VP;

    int tid = threadIdx.x;
    int wid = tid >> 5, lane = tid & 31;
    int g = lane >> 2, qd = lane & 3;
    int bh = blockIdx.y;
    int q0 = blockIdx.x * 128;
    int mrow = wid * 16;

    // load Q tile -> bf16 hi/lo smem
    const float* Qb = g_q + ((size_t)bh * SEQ + q0) * HDIM;
    #pragma unroll
    for (int j = 0; j < 8; j++) {
        int idx = tid + 256 * j;
        int r = idx >> 4, c = (idx & 15) * 4;
        float4 v = *(const float4*)(Qb + r * 64 + c);
        int cb = c >> 1;
        uint32_t h, l;
        split2(v.x, v.y, h, l); Qh[r*QP+cb  ] = h; Ql[r*QP+cb  ] = l;
        split2(v.z, v.w, h, l); Qh[r*QP+cb+1] = h; Ql[r*QP+cb+1] = l;
    }

    float o[8][4] = {};
    float m0 = -1e30f, m1 = -1e30f, l0 = 0.f, l1 = 0.f;

    for (int kt = 0; kt < SEQ / 64; kt++) {
        __syncthreads();   // previous iteration's K/Vt readers done
        const float* Kb = g_k + ((size_t)bh * SEQ + kt * 64) * HDIM;
        const float* Vb = g_v + ((size_t)bh * SEQ + kt * 64) * HDIM;
        // K tile (row-major, pairs along d)
        #pragma unroll
        for (int j = 0; j < 4; j++) {
            int idx = tid + 256 * j;
            int r = idx >> 4, c = (idx & 15) * 4;
            float4 kv = *(const float4*)(Kb + r * 64 + c);
            int cb = c >> 1;
            uint32_t h, l;
            split2(kv.x, kv.y, h, l); Kh[r*KP+cb  ] = h; Kl[r*KP+cb  ] = l;
            split2(kv.z, kv.w, h, l); Kh[r*KP+cb+1] = h; Kl[r*KP+cb+1] = l;
        }
        // V tile transposed: Vt[d][kv-pair]
        #pragma unroll
        for (int i = 0; i < 4; i++) {
            int p2 = (tid >> 5) + 8 * i;       // kv pair index
            int c  = (lane) * 2;                // d col
            float2 v0 = *(const float2*)(Vb + (2*p2    ) * 64 + c);
            float2 v1 = *(const float2*)(Vb + (2*p2 + 1) * 64 + c);
            uint32_t h, l;
            split2(v0.x, v1.x, h, l); Vth[ c   *VP + p2] = h; Vtl[ c   *VP + p2] = l;
            split2(v0.y, v1.y, h, l); Vth[(c+1)*VP + p2] = h; Vtl[(c+1)*VP + p2] = l;
        }
        __syncthreads();

        // S = Q @ K^T  (16 x 64 per warp), bf16x3
        float s[8][4] = {};
        #pragma unroll
        for (int chunk = 0; chunk < 4; chunk++) {
            int u0 = 8 * chunk;
            uint32_t ah[4], al_[4];
            int abase = (mrow + g) * QP + u0 + qd;
            ah [0] = Qh[abase];          ah [1] = Qh[abase + 8*QP];
            ah [2] = Qh[abase + 4];      ah [3] = Qh[abase + 8*QP + 4];
            al_[0] = Ql[abase];          al_[1] = Ql[abase + 8*QP];
            al_[2] = Ql[abase + 4];      al_[3] = Ql[abase + 8*QP + 4];
            uint32_t bh_[8][2], bl_[8][2];
            #pragma unroll
            for (int ni = 0; ni < 8; ni++) {
                int bbase = (8*ni + g) * KP + u0 + qd;
                bh_[ni][0] = Kh[bbase]; bh_[ni][1] = Kh[bbase + 4];
                bl_[ni][0] = Kl[bbase]; bl_[ni][1] = Kl[bbase + 4];
            }
            #pragma unroll
            for (int ni = 0; ni < 8; ni++) mma16(s[ni], ah,  bh_[ni][0], bh_[ni][1]);
            #pragma unroll
            for (int ni = 0; ni < 8; ni++) mma16(s[ni], al_, bh_[ni][0], bh_[ni][1]);
            #pragma unroll
            for (int ni = 0; ni < 8; ni++) mma16(s[ni], ah,  bl_[ni][0], bl_[ni][1]);
        }
        #pragma unroll
        for (int ni = 0; ni < 8; ni++)
            #pragma unroll
            for (int j = 0; j < 4; j++) s[ni][j] *= INV_SCALE;

        // online softmax (rows g and g+8)
        float t0 = -1e30f, t1 = -1e30f;
        #pragma unroll
        for (int ni = 0; ni < 8; ni++) {
            t0 = fmaxf(t0, fmaxf(s[ni][0], s[ni][1]));
            t1 = fmaxf(t1, fmaxf(s[ni][2], s[ni][3]));
        }
        t0 = fmaxf(t0, __shfl_xor_sync(0xffffffffu, t0, 1));
        t0 = fmaxf(t0, __shfl_xor_sync(0xffffffffu, t0, 2));
        t1 = fmaxf(t1, __shfl_xor_sync(0xffffffffu, t1, 1));
        t1 = fmaxf(t1, __shfl_xor_sync(0xffffffffu, t1, 2));
        float mn0 = fmaxf(m0, t0), mn1 = fmaxf(m1, t1);
        float a0 = __expf(m0 - mn0), a1 = __expf(m1 - mn1);
        m0 = mn0; m1 = mn1;
        float p0 = 0.f, p1 = 0.f;
        #pragma unroll
        for (int ni = 0; ni < 8; ni++) {
            s[ni][0] = __expf(s[ni][0] - mn0); p0 += s[ni][0];
            s[ni][1] = __expf(s[ni][1] - mn0); p0 += s[ni][1];
            s[ni][2] = __expf(s[ni][2] - mn1); p1 += s[ni][2];
            s[ni][3] = __expf(s[ni][3] - mn1); p1 += s[ni][3];
        }
        p0 += __shfl_xor_sync(0xffffffffu, p0, 1);
        p0 += __shfl_xor_sync(0xffffffffu, p0, 2);
        p1 += __shfl_xor_sync(0xffffffffu, p1, 1);
        p1 += __shfl_xor_sync(0xffffffffu, p1, 2);
        l0 = l0 * a0 + p0;
        l1 = l1 * a1 + p1;
        #pragma unroll
        for (int ni = 0; ni < 8; ni++) {
            o[ni][0] *= a0; o[ni][1] *= a0;
            o[ni][2] *= a1; o[ni][3] *= a1;
        }

        // P -> bf16 hi/lo A-fragments ENTIRELY in registers
        // (C frag of S tiles 2nj,2nj+1 == A frag for k-chunk nj)
        uint32_t ph[4][4], pl[4][4];
        #pragma unroll
        for (int nj = 0; nj < 4; nj++) {
            split2(s[2*nj  ][0], s[2*nj  ][1], ph[nj][0], pl[nj][0]);
            split2(s[2*nj  ][2], s[2*nj  ][3], ph[nj][1], pl[nj][1]);
            split2(s[2*nj+1][0], s[2*nj+1][1], ph[nj][2], pl[nj][2]);
            split2(s[2*nj+1][2], s[2*nj+1][3], ph[nj][3], pl[nj][3]);
        }

        // O += P @ V  (k over kv, 4 chunks of 16)
        #pragma unroll
        for (int nj = 0; nj < 4; nj++) {
            uint32_t bvh[8][2], bvl[8][2];
            #pragma unroll
            for (int ni = 0; ni < 8; ni++) {
                int bbase = (8*ni + g) * VP + 8*nj + qd;
                bvh[ni][0] = Vth[bbase]; bvh[ni][1] = Vth[bbase + 4];
                bvl[ni][0] = Vtl[bbase]; bvl[ni][1] = Vtl[bbase + 4];
            }
            #pragma unroll
            for (int ni = 0; ni < 8; ni++) mma16(o[ni], ph[nj], bvh[ni][0], bvh[ni][1]);
            #pragma unroll
            for (int ni = 0; ni < 8; ni++) mma16(o[ni], pl[nj], bvh[ni][0], bvh[ni][1]);
            #pragma unroll
            for (int ni = 0; ni < 8; ni++) mma16(o[ni], ph[nj], bvl[ni][0], bvl[ni][1]);
        }
    }

    // final: divide by l, write merged-head layout
    float inv0 = 1.f / l0, inv1 = 1.f / l1;
    int b = bh >> 4, h = bh & 15;
    int n0 = q0 + mrow + g;
    #pragma unroll
    for (int ni = 0; ni < 8; ni++) {
        int col = h * HDIM + 8*ni + 2*qd;
        Out[((size_t)b * SEQ + n0) * DIM + col    ] = o[ni][0] * inv0;
        Out[((size_t)b * SEQ + n0) * DIM + col + 1] = o[ni][1] * inv0;
        Out[((size_t)b * SEQ + n0 + 8) * DIM + col    ] = o[ni][2] * inv1;
        Out[((size_t)b * SEQ + n0 + 8) * DIM + col + 1] = o[ni][3] * inv1;
    }
}

// ---------------- launch ----------------
extern "C" void kernel_launch(void* const* d_in, const int* in_sizes, int n_in,
                              void* d_out, int out_size)
{
    const float* z        = (const float*)d_in[0];
    const float* ln_scale = (const float*)d_in[1];
    const float* ln_bias  = (const float*)d_in[2];
    const float* w_qkv    = (const float*)d_in[3];
    const float* w_proj   = (const float*)d_in[4];
    const float* b_proj   = (const float*)d_in[5];
    float* out = (float*)d_out;

    float *zn, *att;
    cudaGetSymbolAddress((void**)&zn,  g_zn);
    cudaGetSymbolAddress((void**)&att, g_att);

    cudaFuncSetAttribute(gemm_bf16<0>, cudaFuncAttributeMaxDynamicSharedMemorySize, GEMM_SMEM_BYTES);
    cudaFuncSetAttribute(gemm_bf16<1>, cudaFuncAttributeMaxDynamicSharedMemorySize, GEMM_SMEM_BYTES);
    cudaFuncSetAttribute(attn_bf16,    cudaFuncAttributeMaxDynamicSharedMemorySize, ATTN_SMEM_BYTES);

    // 1) LayerNorm
    ln_kernel<<<ROWS, 256>>>(z, ln_scale, ln_bias, zn);

    // 2) QKV GEMM with de-interleave scatter epilogue
    gemm_bf16<0><<<dim3(QKVN / 128, ROWS / 128), 256, GEMM_SMEM_BYTES>>>(
        zn, w_qkv, nullptr, nullptr, nullptr, ROWS, QKVN, DIM);

    // 3) attention (bf16x3 flash, register-resident P)
    attn_bf16<<<dim3(SEQ / 128, BATCH * HEADS), 256, ATTN_SMEM_BYTES>>>(att);

    // 4) output projection + bias + residual
    gemm_bf16<1><<<dim3(DIM / 128, ROWS / 128), 256, GEMM_SMEM_BYTES>>>(
        att, w_proj, out, z, b_proj, ROWS, DIM, DIM);
}

// round 6
// speedup vs baseline: 2.7613x; 1.3904x over previous
#include <cuda_runtime.h>
#include <cuda_fp16.h>
#include <math.h>
#include <stdint.h>

#define BATCH 2
#define SEQ   2048
#define DIM   1024
#define HEADS 16
#define HDIM  64
#define ROWS  (BATCH * SEQ)      // 4096
#define QKVN  (3 * DIM)          // 3072
#define EPS   1e-5f
#define INV_SCALE 0.125f         // 1/sqrt(64)

// ---------------- scratch (__device__ globals: no allocation allowed) --------
__device__ float g_zn [ROWS * DIM];
__device__ float g_q  [ROWS * DIM];   // [B*H, N, HD]
__device__ float g_k  [ROWS * DIM];
__device__ float g_v  [ROWS * DIM];
__device__ float g_att[ROWS * DIM];   // attention out [4096,1024]

// ---------------- fp16 helpers ----------------
// split two floats into packed half2 hi and packed half2 lo residual
__device__ __forceinline__ void split2h(float x, float y, uint32_t& h, uint32_t& l) {
    __half hx = __float2half_rn(x);
    __half hy = __float2half_rn(y);
    __half lx = __float2half_rn(x - __half2float(hx));
    __half ly = __float2half_rn(y - __half2float(hy));
    __half2 hh = __halves2half2(hx, hy);
    __half2 ll = __halves2half2(lx, ly);
    h = *reinterpret_cast<uint32_t*>(&hh);
    l = *reinterpret_cast<uint32_t*>(&ll);
}
// pack two floats to half2 (hi only)
__device__ __forceinline__ uint32_t pack2h(float x, float y) {
    __half2 hh = __halves2half2(__float2half_rn(x), __float2half_rn(y));
    return *reinterpret_cast<uint32_t*>(&hh);
}
// D += A(16x16) * B(16x8), fp16 in, fp32 accum
__device__ __forceinline__ void mma16(float* c, const uint32_t* a, uint32_t b0, uint32_t b1) {
    asm volatile(
        "mma.sync.aligned.m16n8k16.row.col.f32.f16.f16.f32 "
        "{%0,%1,%2,%3}, {%4,%5,%6,%7}, {%8,%9}, {%0,%1,%2,%3};"
        : "+f"(c[0]), "+f"(c[1]), "+f"(c[2]), "+f"(c[3])
        : "r"(a[0]), "r"(a[1]), "r"(a[2]), "r"(a[3]), "r"(b0), "r"(b1));
}

// ---------------- LayerNorm ----------------
__global__ __launch_bounds__(256) void ln_kernel(
    const float* __restrict__ z, const float* __restrict__ sc,
    const float* __restrict__ bi, float* __restrict__ out)
{
    int row = blockIdx.x;
    int t = threadIdx.x;
    const float4 v = ((const float4*)(z + row * DIM))[t];
    float s  = v.x + v.y + v.z + v.w;
    float s2 = v.x*v.x + v.y*v.y + v.z*v.z + v.w*v.w;

    __shared__ float ssum[8], ssum2[8], stats[2];
    #pragma unroll
    for (int off = 16; off > 0; off >>= 1) {
        s  += __shfl_down_sync(0xffffffffu, s,  off);
        s2 += __shfl_down_sync(0xffffffffu, s2, off);
    }
    int lane = t & 31, wid = t >> 5;
    if (lane == 0) { ssum[wid] = s; ssum2[wid] = s2; }
    __syncthreads();
    if (t == 0) {
        float a = 0.f, b = 0.f;
        #pragma unroll
        for (int i = 0; i < 8; i++) { a += ssum[i]; b += ssum2[i]; }
        float mu  = a * (1.0f / DIM);
        float var = b * (1.0f / DIM) - mu * mu;
        stats[0] = mu;
        stats[1] = rsqrtf(var + EPS);
    }
    __syncthreads();
    float mu = stats[0], rstd = stats[1];
    float4 s4 = ((const float4*)sc)[t];
    float4 b4 = ((const float4*)bi)[t];
    float4 r;
    r.x = (v.x - mu) * rstd * s4.x + b4.x;
    r.y = (v.y - mu) * rstd * s4.y + b4.y;
    r.z = (v.z - mu) * rstd * s4.z + b4.z;
    r.w = (v.w - mu) * rstd * s4.w + b4.w;
    ((float4*)(out + row * DIM))[t] = r;
}

// ---------------- fp16x2 GEMM: 128x128 tile, k-step 32, 8 warps (2x4) -------
// A smem hi+lo: [128 rows][16 uint k-pairs]; B smem hi only, transposed.
#define AP 36
#define BP 37
#define GEMM_SMEM_BYTES ((2 * 128 * AP + 128 * BP) * 4)

template<int MODE>
__global__ __launch_bounds__(256) void gemm_fp16(
    const float* __restrict__ A, const float* __restrict__ B,
    float* __restrict__ C, const float* __restrict__ zres,
    const float* __restrict__ bias, int M, int Ncols, int K)
{
    extern __shared__ uint32_t smg[];
    uint32_t* Ah  = smg;
    uint32_t* Al  = Ah  + 128 * AP;
    uint32_t* Bth = Al  + 128 * AP;

    int tid = threadIdx.x;
    int wid = tid >> 5, lane = tid & 31;
    int wm = wid >> 2, wn = wid & 3;       // 2x4 warp grid
    int g = lane >> 2, qd = lane & 3;
    int bm = blockIdx.y * 128, bn = blockIdx.x * 128;

    int aR0 = tid >> 3;                    // A row (+32*i)
    int aC0 = (tid & 7) * 4;               // A col in k-tile (even)
    int bP0 = tid >> 5;                    // B k-pair (+8*i)
    int bC0 = (tid & 31) * 4;              // B n-col

    float acc[4][4][4] = {};
    float4 aReg[4], bReg[2][2];

    #pragma unroll
    for (int i = 0; i < 4; i++)
        aReg[i] = *(const float4*)(A + (size_t)(bm + aR0 + 32*i) * K + aC0);
    #pragma unroll
    for (int i = 0; i < 2; i++)
        #pragma unroll
        for (int r = 0; r < 2; r++)
            bReg[i][r] = *(const float4*)(B + (size_t)(2*(bP0 + 8*i) + r) * Ncols + bn + bC0);

    auto storeAB = [&]() {
        #pragma unroll
        for (int i = 0; i < 4; i++) {
            int r = aR0 + 32*i;
            int cb = aC0 >> 1;
            uint32_t h, l;
            split2h(aReg[i].x, aReg[i].y, h, l); Ah[r*AP+cb  ] = h; Al[r*AP+cb  ] = l;
            split2h(aReg[i].z, aReg[i].w, h, l); Ah[r*AP+cb+1] = h; Al[r*AP+cb+1] = l;
        }
        #pragma unroll
        for (int i = 0; i < 2; i++) {
            int p = bP0 + 8*i;
            const float* r0 = (const float*)&bReg[i][0];
            const float* r1 = (const float*)&bReg[i][1];
            #pragma unroll
            for (int j = 0; j < 4; j++)
                Bth[(bC0 + j)*BP + p] = pack2h(r0[j], r1[j]);
        }
    };

    storeAB();
    __syncthreads();

    for (int kk = 0; kk < K; kk += 32) {
        bool more = (kk + 32) < K;
        if (more) {
            #pragma unroll
            for (int i = 0; i < 4; i++)
                aReg[i] = *(const float4*)(A + (size_t)(bm + aR0 + 32*i) * K + kk + 32 + aC0);
            #pragma unroll
            for (int i = 0; i < 2; i++)
                #pragma unroll
                for (int r = 0; r < 2; r++)
                    bReg[i][r] = *(const float4*)(B + (size_t)(kk + 32 + 2*(bP0 + 8*i) + r) * Ncols + bn + bC0);
        }

        #pragma unroll
        for (int chunk = 0; chunk < 2; chunk++) {
            int u0 = 8 * chunk;
            uint32_t ah[4][4], al_[4][4];
            #pragma unroll
            for (int mi = 0; mi < 4; mi++) {
                int base = (64*wm + 16*mi + g) * AP + u0 + qd;
                ah [mi][0] = Ah[base];          ah [mi][1] = Ah[base + 8*AP];
                ah [mi][2] = Ah[base + 4];      ah [mi][3] = Ah[base + 8*AP + 4];
                al_[mi][0] = Al[base];          al_[mi][1] = Al[base + 8*AP];
                al_[mi][2] = Al[base + 4];      al_[mi][3] = Al[base + 8*AP + 4];
            }
            uint32_t bh[4][2];
            #pragma unroll
            for (int ni = 0; ni < 4; ni++) {
                int base = (32*wn + 8*ni + g) * BP + u0 + qd;
                bh[ni][0] = Bth[base]; bh[ni][1] = Bth[base + 4];
            }
            // 2 term passes, 16 independent accumulators each
            #pragma unroll
            for (int mi = 0; mi < 4; mi++)
                #pragma unroll
                for (int ni = 0; ni < 4; ni++)
                    mma16(acc[mi][ni], ah[mi], bh[ni][0], bh[ni][1]);
            #pragma unroll
            for (int mi = 0; mi < 4; mi++)
                #pragma unroll
                for (int ni = 0; ni < 4; ni++)
                    mma16(acc[mi][ni], al_[mi], bh[ni][0], bh[ni][1]);
        }

        if (more) {
            __syncthreads();
            storeAB();
            __syncthreads();
        }
    }

    // epilogue
    #pragma unroll
    for (int mi = 0; mi < 4; mi++)
        #pragma unroll
        for (int ni = 0; ni < 4; ni++)
            #pragma unroll
            for (int j = 0; j < 4; j++) {
                int gm = bm + 64*wm + 16*mi + g + ((j >> 1) << 3);
                int gn = bn + 32*wn + 8*ni + 2*qd + (j & 1);
                if (MODE == 0) {
                    int bb = gm >> 11;
                    int nn = gm & (SEQ - 1);
                    int h   = gn / 192;
                    int rem = gn - h * 192;
                    int d   = rem / 3;
                    int w   = rem - d * 3;
                    float* dst = (w == 0) ? g_q : (w == 1) ? g_k : g_v;
                    dst[(((size_t)bb * HEADS + h) * SEQ + nn) * HDIM + d] = acc[mi][ni][j];
                } else {
                    size_t idx = (size_t)gm * Ncols + gn;
                    C[idx] = acc[mi][ni][j] + bias[gn] + zres[idx];
                }
            }
}

// ---------------- fp16x2 flash attention, P kept in registers ----------------
// 256 thr (8 warps), tile 128 q x 64 kv, HD=64. Warp w owns q rows [16w,16w+16).
#define QP 36
#define KP 36
#define VP 35
#define ATTN_SMEM_BYTES ((2*128*QP + 64*KP + 64*VP) * 4)

__global__ __launch_bounds__(256) void attn_fp16(float* __restrict__ Out)
{
    extern __shared__ uint32_t sma[];
    uint32_t* Qh  = sma;
    uint32_t* Ql  = Qh  + 128 * QP;
    uint32_t* Kh  = Ql  + 128 * QP;
    uint32_t* Vth = Kh  + 64 * KP;

    int tid = threadIdx.x;
    int wid = tid >> 5, lane = tid & 31;
    int g = lane >> 2, qd = lane & 3;
    int bh = blockIdx.y;
    int q0 = blockIdx.x * 128;
    int mrow = wid * 16;

    // load Q tile -> fp16 hi/lo smem
    const float* Qb = g_q + ((size_t)bh * SEQ + q0) * HDIM;
    #pragma unroll
    for (int j = 0; j < 8; j++) {
        int idx = tid + 256 * j;
        int r = idx >> 4, c = (idx & 15) * 4;
        float4 v = *(const float4*)(Qb + r * 64 + c);
        int cb = c >> 1;
        uint32_t h, l;
        split2h(v.x, v.y, h, l); Qh[r*QP+cb  ] = h; Ql[r*QP+cb  ] = l;
        split2h(v.z, v.w, h, l); Qh[r*QP+cb+1] = h; Ql[r*QP+cb+1] = l;
    }

    float o[8][4] = {};
    float m0 = -1e30f, m1 = -1e30f, l0 = 0.f, l1 = 0.f;

    for (int kt = 0; kt < SEQ / 64; kt++) {
        __syncthreads();   // previous iteration's K/Vt readers done
        const float* Kb = g_k + ((size_t)bh * SEQ + kt * 64) * HDIM;
        const float* Vb = g_v + ((size_t)bh * SEQ + kt * 64) * HDIM;
        // K tile (row-major, pairs along d) — hi only
        #pragma unroll
        for (int j = 0; j < 4; j++) {
            int idx = tid + 256 * j;
            int r = idx >> 4, c = (idx & 15) * 4;
            float4 kv = *(const float4*)(Kb + r * 64 + c);
            int cb = c >> 1;
            Kh[r*KP+cb  ] = pack2h(kv.x, kv.y);
            Kh[r*KP+cb+1] = pack2h(kv.z, kv.w);
        }
        // V tile transposed: Vt[d][kv-pair] — hi only
        #pragma unroll
        for (int i = 0; i < 4; i++) {
            int p2 = (tid >> 5) + 8 * i;       // kv pair index
            int c  = (lane) * 2;                // d col
            float2 v0 = *(const float2*)(Vb + (2*p2    ) * 64 + c);
            float2 v1 = *(const float2*)(Vb + (2*p2 + 1) * 64 + c);
            Vth[ c   *VP + p2] = pack2h(v0.x, v1.x);
            Vth[(c+1)*VP + p2] = pack2h(v0.y, v1.y);
        }
        __syncthreads();

        // S = Q @ K^T (16 x 64 per warp), fp16x2
        float s[8][4] = {};
        #pragma unroll
        for (int chunk = 0; chunk < 4; chunk++) {
            int u0 = 8 * chunk;
            uint32_t ah[4], al_[4];
            int abase = (mrow + g) * QP + u0 + qd;
            ah [0] = Qh[abase];          ah [1] = Qh[abase + 8*QP];
            ah [2] = Qh[abase + 4];      ah [3] = Qh[abase + 8*QP + 4];
            al_[0] = Ql[abase];          al_[1] = Ql[abase + 8*QP];
            al_[2] = Ql[abase + 4];      al_[3] = Ql[abase + 8*QP + 4];
            uint32_t bh_[8][2];
            #pragma unroll
            for (int ni = 0; ni < 8; ni++) {
                int bbase = (8*ni + g) * KP + u0 + qd;
                bh_[ni][0] = Kh[bbase]; bh_[ni][1] = Kh[bbase + 4];
            }
            #pragma unroll
            for (int ni = 0; ni < 8; ni++) mma16(s[ni], ah,  bh_[ni][0], bh_[ni][1]);
            #pragma unroll
            for (int ni = 0; ni < 8; ni++) mma16(s[ni], al_, bh_[ni][0], bh_[ni][1]);
        }
        #pragma unroll
        for (int ni = 0; ni < 8; ni++)
            #pragma unroll
            for (int j = 0; j < 4; j++) s[ni][j] *= INV_SCALE;

        // online softmax (rows g and g+8)
        float t0 = -1e30f, t1 = -1e30f;
        #pragma unroll
        for (int ni = 0; ni < 8; ni++) {
            t0 = fmaxf(t0, fmaxf(s[ni][0], s[ni][1]));
            t1 = fmaxf(t1, fmaxf(s[ni][2], s[ni][3]));
        }
        t0 = fmaxf(t0, __shfl_xor_sync(0xffffffffu, t0, 1));
        t0 = fmaxf(t0, __shfl_xor_sync(0xffffffffu, t0, 2));
        t1 = fmaxf(t1, __shfl_xor_sync(0xffffffffu, t1, 1));
        t1 = fmaxf(t1, __shfl_xor_sync(0xffffffffu, t1, 2));
        float mn0 = fmaxf(m0, t0), mn1 = fmaxf(m1, t1);
        float a0 = __expf(m0 - mn0), a1 = __expf(m1 - mn1);
        m0 = mn0; m1 = mn1;
        float p0 = 0.f, p1 = 0.f;
        #pragma unroll
        for (int ni = 0; ni < 8; ni++) {
            s[ni][0] = __expf(s[ni][0] - mn0); p0 += s[ni][0];
            s[ni][1] = __expf(s[ni][1] - mn0); p0 += s[ni][1];
            s[ni][2] = __expf(s[ni][2] - mn1); p1 += s[ni][2];
            s[ni][3] = __expf(s[ni][3] - mn1); p1 += s[ni][3];
        }
        p0 += __shfl_xor_sync(0xffffffffu, p0, 1);
        p0 += __shfl_xor_sync(0xffffffffu, p0, 2);
        p1 += __shfl_xor_sync(0xffffffffu, p1, 1);
        p1 += __shfl_xor_sync(0xffffffffu, p1, 2);
        l0 = l0 * a0 + p0;
        l1 = l1 * a1 + p1;
        #pragma unroll
        for (int ni = 0; ni < 8; ni++) {
            o[ni][0] *= a0; o[ni][1] *= a0;
            o[ni][2] *= a1; o[ni][3] *= a1;
        }

        // P -> fp16 hi/lo A-fragments in registers
        uint32_t ph[4][4], pl[4][4];
        #pragma unroll
        for (int nj = 0; nj < 4; nj++) {
            split2h(s[2*nj  ][0], s[2*nj  ][1], ph[nj][0], pl[nj][0]);
            split2h(s[2*nj  ][2], s[2*nj  ][3], ph[nj][1], pl[nj][1]);
            split2h(s[2*nj+1][0], s[2*nj+1][1], ph[nj][2], pl[nj][2]);
            split2h(s[2*nj+1][2], s[2*nj+1][3], ph[nj][3], pl[nj][3]);
        }

        // O += P @ V (k over kv, 4 chunks of 16)
        #pragma unroll
        for (int nj = 0; nj < 4; nj++) {
            uint32_t bvh[8][2];
            #pragma unroll
            for (int ni = 0; ni < 8; ni++) {
                int bbase = (8*ni + g) * VP + 8*nj + qd;
                bvh[ni][0] = Vth[bbase]; bvh[ni][1] = Vth[bbase + 4];
            }
            #pragma unroll
            for (int ni = 0; ni < 8; ni++) mma16(o[ni], ph[nj], bvh[ni][0], bvh[ni][1]);
            #pragma unroll
            for (int ni = 0; ni < 8; ni++) mma16(o[ni], pl[nj], bvh[ni][0], bvh[ni][1]);
        }
    }

    // final: divide by l, write merged-head layout
    float inv0 = 1.f / l0, inv1 = 1.f / l1;
    int b = bh >> 4, h = bh & 15;
    int n0 = q0 + mrow + g;
    #pragma unroll
    for (int ni = 0; ni < 8; ni++) {
        int col = h * HDIM + 8*ni + 2*qd;
        Out[((size_t)b * SEQ + n0) * DIM + col    ] = o[ni][0] * inv0;
        Out[((size_t)b * SEQ + n0) * DIM + col + 1] = o[ni][1] * inv0;
        Out[((size_t)b * SEQ + n0 + 8) * DIM + col    ] = o[ni][2] * inv1;
        Out[((size_t)b * SEQ + n0 + 8) * DIM + col + 1] = o[ni][3] * inv1;
    }
}

// ---------------- launch ----------------
extern "C" void kernel_launch(void* const* d_in, const int* in_sizes, int n_in,
                              void* d_out, int out_size)
{
    const float* z        = (const float*)d_in[0];
    const float* ln_scale = (const float*)d_in[1];
    const float* ln_bias  = (const float*)d_in[2];
    const float* w_qkv    = (const float*)d_in[3];
    const float* w_proj   = (const float*)d_in[4];
    const float* b_proj   = (const float*)d_in[5];
    float* out = (float*)d_out;

    float *zn, *att;
    cudaGetSymbolAddress((void**)&zn,  g_zn);
    cudaGetSymbolAddress((void**)&att, g_att);

    cudaFuncSetAttribute(gemm_fp16<0>, cudaFuncAttributeMaxDynamicSharedMemorySize, GEMM_SMEM_BYTES);
    cudaFuncSetAttribute(gemm_fp16<1>, cudaFuncAttributeMaxDynamicSharedMemorySize, GEMM_SMEM_BYTES);
    cudaFuncSetAttribute(attn_fp16,    cudaFuncAttributeMaxDynamicSharedMemorySize, ATTN_SMEM_BYTES);

    // 1) LayerNorm
    ln_kernel<<<ROWS, 256>>>(z, ln_scale, ln_bias, zn);

    // 2) QKV GEMM with de-interleave scatter epilogue
    gemm_fp16<0><<<dim3(QKVN / 128, ROWS / 128), 256, GEMM_SMEM_BYTES>>>(
        zn, w_qkv, nullptr, nullptr, nullptr, ROWS, QKVN, DIM);

    // 3) attention (fp16x2 flash, register-resident P)
    attn_fp16<<<dim3(SEQ / 128, BATCH * HEADS), 256, ATTN_SMEM_BYTES>>>(att);

    // 4) output projection + bias + residual
    gemm_fp16<1><<<dim3(DIM / 128, ROWS / 128), 256, GEMM_SMEM_BYTES>>>(
        att, w_proj, out, z, b_proj, ROWS, DIM, DIM);
}

// round 7
// speedup vs baseline: 2.9371x; 1.0637x over previous
#include <cuda_runtime.h>
#include <cuda_fp16.h>
#include <math.h>
#include <stdint.h>

#define BATCH 2
#define SEQ   2048
#define DIM   1024
#define HEADS 16
#define HDIM  64
#define ROWS  (BATCH * SEQ)      // 4096
#define QKVN  (3 * DIM)          // 3072
#define EPS   1e-5f
#define INV_SCALE 0.125f         // 1/sqrt(64)

// ---------------- scratch (__device__ globals: no allocation allowed) --------
__device__ float g_zn [ROWS * DIM];
__device__ float g_q  [ROWS * DIM];   // [B*H, N, HD]
__device__ float g_k  [ROWS * DIM];
__device__ float g_v  [ROWS * DIM];
__device__ float g_att[ROWS * DIM];   // attention out [4096,1024]

// ---------------- fp16 helpers ----------------
__device__ __forceinline__ void split2h(float x, float y, uint32_t& h, uint32_t& l) {
    __half hx = __float2half_rn(x);
    __half hy = __float2half_rn(y);
    __half lx = __float2half_rn(x - __half2float(hx));
    __half ly = __float2half_rn(y - __half2float(hy));
    __half2 hh = __halves2half2(hx, hy);
    __half2 ll = __halves2half2(lx, ly);
    h = *reinterpret_cast<uint32_t*>(&hh);
    l = *reinterpret_cast<uint32_t*>(&ll);
}
__device__ __forceinline__ uint32_t pack2h(float x, float y) {
    __half2 hh = __halves2half2(__float2half_rn(x), __float2half_rn(y));
    return *reinterpret_cast<uint32_t*>(&hh);
}
__device__ __forceinline__ void mma16(float* c, const uint32_t* a, uint32_t b0, uint32_t b1) {
    asm volatile(
        "mma.sync.aligned.m16n8k16.row.col.f32.f16.f16.f32 "
        "{%0,%1,%2,%3}, {%4,%5,%6,%7}, {%8,%9}, {%0,%1,%2,%3};"
        : "+f"(c[0]), "+f"(c[1]), "+f"(c[2]), "+f"(c[3])
        : "r"(a[0]), "r"(a[1]), "r"(a[2]), "r"(a[3]), "r"(b0), "r"(b1));
}

// ---------------- LayerNorm ----------------
__global__ __launch_bounds__(256) void ln_kernel(
    const float* __restrict__ z, const float* __restrict__ sc,
    const float* __restrict__ bi, float* __restrict__ out)
{
    int row = blockIdx.x;
    int t = threadIdx.x;
    const float4 v = ((const float4*)(z + row * DIM))[t];
    float s  = v.x + v.y + v.z + v.w;
    float s2 = v.x*v.x + v.y*v.y + v.z*v.z + v.w*v.w;

    __shared__ float ssum[8], ssum2[8], stats[2];
    #pragma unroll
    for (int off = 16; off > 0; off >>= 1) {
        s  += __shfl_down_sync(0xffffffffu, s,  off);
        s2 += __shfl_down_sync(0xffffffffu, s2, off);
    }
    int lane = t & 31, wid = t >> 5;
    if (lane == 0) { ssum[wid] = s; ssum2[wid] = s2; }
    __syncthreads();
    if (t == 0) {
        float a = 0.f, b = 0.f;
        #pragma unroll
        for (int i = 0; i < 8; i++) { a += ssum[i]; b += ssum2[i]; }
        float mu  = a * (1.0f / DIM);
        float var = b * (1.0f / DIM) - mu * mu;
        stats[0] = mu;
        stats[1] = rsqrtf(var + EPS);
    }
    __syncthreads();
    float mu = stats[0], rstd = stats[1];
    float4 s4 = ((const float4*)sc)[t];
    float4 b4 = ((const float4*)bi)[t];
    float4 r;
    r.x = (v.x - mu) * rstd * s4.x + b4.x;
    r.y = (v.y - mu) * rstd * s4.y + b4.y;
    r.z = (v.z - mu) * rstd * s4.z + b4.z;
    r.w = (v.w - mu) * rstd * s4.w + b4.w;
    ((float4*)(out + row * DIM))[t] = r;
}

// ---------------- fp16x2 GEMM: 128x128 tile, k-step 32, 8 warps (2x4) -------
// 2 CTAs/SM via launch bounds (occupancy fix).
#define AP 36
#define BP 37
#define GEMM_SMEM_BYTES ((2 * 128 * AP + 128 * BP) * 4)

template<int MODE>
__global__ __launch_bounds__(256, 2) void gemm_fp16(
    const float* __restrict__ A, const float* __restrict__ B,
    float* __restrict__ C, const float* __restrict__ zres,
    const float* __restrict__ bias, int M, int Ncols, int K)
{
    extern __shared__ uint32_t smg[];
    uint32_t* Ah  = smg;
    uint32_t* Al  = Ah  + 128 * AP;
    uint32_t* Bth = Al  + 128 * AP;

    int tid = threadIdx.x;
    int wid = tid >> 5, lane = tid & 31;
    int wm = wid >> 2, wn = wid & 3;       // 2x4 warp grid
    int g = lane >> 2, qd = lane & 3;
    int bm = blockIdx.y * 128, bn = blockIdx.x * 128;

    int aR0 = tid >> 3;                    // A row (+32*i)
    int aC0 = (tid & 7) * 4;               // A col in k-tile (even)
    int bP0 = tid >> 5;                    // B k-pair (+8*i)
    int bC0 = (tid & 31) * 4;              // B n-col

    float acc[4][4][4] = {};
    float4 aReg[4], bReg[2][2];

    #pragma unroll
    for (int i = 0; i < 4; i++)
        aReg[i] = *(const float4*)(A + (size_t)(bm + aR0 + 32*i) * K + aC0);
    #pragma unroll
    for (int i = 0; i < 2; i++)
        #pragma unroll
        for (int r = 0; r < 2; r++)
            bReg[i][r] = *(const float4*)(B + (size_t)(2*(bP0 + 8*i) + r) * Ncols + bn + bC0);

    auto storeAB = [&]() {
        #pragma unroll
        for (int i = 0; i < 4; i++) {
            int r = aR0 + 32*i;
            int cb = aC0 >> 1;
            uint32_t h, l;
            split2h(aReg[i].x, aReg[i].y, h, l); Ah[r*AP+cb  ] = h; Al[r*AP+cb  ] = l;
            split2h(aReg[i].z, aReg[i].w, h, l); Ah[r*AP+cb+1] = h; Al[r*AP+cb+1] = l;
        }
        #pragma unroll
        for (int i = 0; i < 2; i++) {
            int p = bP0 + 8*i;
            const float* r0 = (const float*)&bReg[i][0];
            const float* r1 = (const float*)&bReg[i][1];
            #pragma unroll
            for (int j = 0; j < 4; j++)
                Bth[(bC0 + j)*BP + p] = pack2h(r0[j], r1[j]);
        }
    };

    storeAB();
    __syncthreads();

    for (int kk = 0; kk < K; kk += 32) {
        bool more = (kk + 32) < K;
        if (more) {
            #pragma unroll
            for (int i = 0; i < 4; i++)
                aReg[i] = *(const float4*)(A + (size_t)(bm + aR0 + 32*i) * K + kk + 32 + aC0);
            #pragma unroll
            for (int i = 0; i < 2; i++)
                #pragma unroll
                for (int r = 0; r < 2; r++)
                    bReg[i][r] = *(const float4*)(B + (size_t)(kk + 32 + 2*(bP0 + 8*i) + r) * Ncols + bn + bC0);
        }

        #pragma unroll
        for (int chunk = 0; chunk < 2; chunk++) {
            int u0 = 8 * chunk;
            uint32_t ah[4][4], al_[4][4];
            #pragma unroll
            for (int mi = 0; mi < 4; mi++) {
                int base = (64*wm + 16*mi + g) * AP + u0 + qd;
                ah [mi][0] = Ah[base];          ah [mi][1] = Ah[base + 8*AP];
                ah [mi][2] = Ah[base + 4];      ah [mi][3] = Ah[base + 8*AP + 4];
                al_[mi][0] = Al[base];          al_[mi][1] = Al[base + 8*AP];
                al_[mi][2] = Al[base + 4];      al_[mi][3] = Al[base + 8*AP + 4];
            }
            uint32_t bh[4][2];
            #pragma unroll
            for (int ni = 0; ni < 4; ni++) {
                int base = (32*wn + 8*ni + g) * BP + u0 + qd;
                bh[ni][0] = Bth[base]; bh[ni][1] = Bth[base + 4];
            }
            #pragma unroll
            for (int mi = 0; mi < 4; mi++)
                #pragma unroll
                for (int ni = 0; ni < 4; ni++)
                    mma16(acc[mi][ni], ah[mi], bh[ni][0], bh[ni][1]);
            #pragma unroll
            for (int mi = 0; mi < 4; mi++)
                #pragma unroll
                for (int ni = 0; ni < 4; ni++)
                    mma16(acc[mi][ni], al_[mi], bh[ni][0], bh[ni][1]);
        }

        if (more) {
            __syncthreads();
            storeAB();
            __syncthreads();
        }
    }

    // epilogue
    #pragma unroll
    for (int mi = 0; mi < 4; mi++)
        #pragma unroll
        for (int ni = 0; ni < 4; ni++)
            #pragma unroll
            for (int j = 0; j < 4; j++) {
                int gm = bm + 64*wm + 16*mi + g + ((j >> 1) << 3);
                int gn = bn + 32*wn + 8*ni + 2*qd + (j & 1);
                if (MODE == 0) {
                    int bb = gm >> 11;
                    int nn = gm & (SEQ - 1);
                    int h   = gn / 192;
                    int rem = gn - h * 192;
                    int d   = rem / 3;
                    int w   = rem - d * 3;
                    float* dst = (w == 0) ? g_q : (w == 1) ? g_k : g_v;
                    dst[(((size_t)bb * HEADS + h) * SEQ + nn) * HDIM + d] = acc[mi][ni][j];
                } else {
                    size_t idx = (size_t)gm * Ncols + gn;
                    C[idx] = acc[mi][ni][j] + bias[gn] + zres[idx];
                }
            }
}

// ---------------- fp16x2 flash attention, P kept in registers ----------------
// 256 thr (8 warps), tile 128 q x 64 kv, HD=64; 2 CTAs/SM.
#define QP 36
#define KP 36
#define VP 35
#define ATTN_SMEM_BYTES ((2*128*QP + 64*KP + 64*VP) * 4)

__global__ __launch_bounds__(256, 2) void attn_fp16(float* __restrict__ Out)
{
    extern __shared__ uint32_t sma[];
    uint32_t* Qh  = sma;
    uint32_t* Ql  = Qh  + 128 * QP;
    uint32_t* Kh  = Ql  + 128 * QP;
    uint32_t* Vth = Kh  + 64 * KP;

    int tid = threadIdx.x;
    int wid = tid >> 5, lane = tid & 31;
    int g = lane >> 2, qd = lane & 3;
    int bh = blockIdx.y;
    int q0 = blockIdx.x * 128;
    int mrow = wid * 16;

    const float* Qb = g_q + ((size_t)bh * SEQ + q0) * HDIM;
    #pragma unroll
    for (int j = 0; j < 8; j++) {
        int idx = tid + 256 * j;
        int r = idx >> 4, c = (idx & 15) * 4;
        float4 v = *(const float4*)(Qb + r * 64 + c);
        int cb = c >> 1;
        uint32_t h, l;
        split2h(v.x, v.y, h, l); Qh[r*QP+cb  ] = h; Ql[r*QP+cb  ] = l;
        split2h(v.z, v.w, h, l); Qh[r*QP+cb+1] = h; Ql[r*QP+cb+1] = l;
    }

    float o[8][4] = {};
    float m0 = -1e30f, m1 = -1e30f, l0 = 0.f, l1 = 0.f;

    for (int kt = 0; kt < SEQ / 64; kt++) {
        __syncthreads();
        const float* Kb = g_k + ((size_t)bh * SEQ + kt * 64) * HDIM;
        const float* Vb = g_v + ((size_t)bh * SEQ + kt * 64) * HDIM;
        #pragma unroll
        for (int j = 0; j < 4; j++) {
            int idx = tid + 256 * j;
            int r = idx >> 4, c = (idx & 15) * 4;
            float4 kv = *(const float4*)(Kb + r * 64 + c);
            int cb = c >> 1;
            Kh[r*KP+cb  ] = pack2h(kv.x, kv.y);
            Kh[r*KP+cb+1] = pack2h(kv.z, kv.w);
        }
        #pragma unroll
        for (int i = 0; i < 4; i++) {
            int p2 = (tid >> 5) + 8 * i;
            int c  = (lane) * 2;
            float2 v0 = *(const float2*)(Vb + (2*p2    ) * 64 + c);
            float2 v1 = *(const float2*)(Vb + (2*p2 + 1) * 64 + c);
            Vth[ c   *VP + p2] = pack2h(v0.x, v1.x);
            Vth[(c+1)*VP + p2] = pack2h(v0.y, v1.y);
        }
        __syncthreads();

        float s[8][4] = {};
        #pragma unroll
        for (int chunk = 0; chunk < 4; chunk++) {
            int u0 = 8 * chunk;
            uint32_t ah[4], al_[4];
            int abase = (mrow + g) * QP + u0 + qd;
            ah [0] = Qh[abase];          ah [1] = Qh[abase + 8*QP];
            ah [2] = Qh[abase + 4];      ah [3] = Qh[abase + 8*QP + 4];
            al_[0] = Ql[abase];          al_[1] = Ql[abase + 8*QP];
            al_[2] = Ql[abase + 4];      al_[3] = Ql[abase + 8*QP + 4];
            uint32_t bh_[8][2];
            #pragma unroll
            for (int ni = 0; ni < 8; ni++) {
                int bbase = (8*ni + g) * KP + u0 + qd;
                bh_[ni][0] = Kh[bbase]; bh_[ni][1] = Kh[bbase + 4];
            }
            #pragma unroll
            for (int ni = 0; ni < 8; ni++) mma16(s[ni], ah,  bh_[ni][0], bh_[ni][1]);
            #pragma unroll
            for (int ni = 0; ni < 8; ni++) mma16(s[ni], al_, bh_[ni][0], bh_[ni][1]);
        }
        #pragma unroll
        for (int ni = 0; ni < 8; ni++)
            #pragma unroll
            for (int j = 0; j < 4; j++) s[ni][j] *= INV_SCALE;

        float t0 = -1e30f, t1 = -1e30f;
        #pragma unroll
        for (int ni = 0; ni < 8; ni++) {
            t0 = fmaxf(t0, fmaxf(s[ni][0], s[ni][1]));
            t1 = fmaxf(t1, fmaxf(s[ni][2], s[ni][3]));
        }
        t0 = fmaxf(t0, __shfl_xor_sync(0xffffffffu, t0, 1));
        t0 = fmaxf(t0, __shfl_xor_sync(0xffffffffu, t0, 2));
        t1 = fmaxf(t1, __shfl_xor_sync(0xffffffffu, t1, 1));
        t1 = fmaxf(t1, __shfl_xor_sync(0xffffffffu, t1, 2));
        float mn0 = fmaxf(m0, t0), mn1 = fmaxf(m1, t1);
        float a0 = __expf(m0 - mn0), a1 = __expf(m1 - mn1);
        m0 = mn0; m1 = mn1;
        float p0 = 0.f, p1 = 0.f;
        #pragma unroll
        for (int ni = 0; ni < 8; ni++) {
            s[ni][0] = __expf(s[ni][0] - mn0); p0 += s[ni][0];
            s[ni][1] = __expf(s[ni][1] - mn0); p0 += s[ni][1];
            s[ni][2] = __expf(s[ni][2] - mn1); p1 += s[ni][2];
            s[ni][3] = __expf(s[ni][3] - mn1); p1 += s[ni][3];
        }
        p0 += __shfl_xor_sync(0xffffffffu, p0, 1);
        p0 += __shfl_xor_sync(0xffffffffu, p0, 2);
        p1 += __shfl_xor_sync(0xffffffffu, p1, 1);
        p1 += __shfl_xor_sync(0xffffffffu, p1, 2);
        l0 = l0 * a0 + p0;
        l1 = l1 * a1 + p1;
        #pragma unroll
        for (int ni = 0; ni < 8; ni++) {
            o[ni][0] *= a0; o[ni][1] *= a0;
            o[ni][2] *= a1; o[ni][3] *= a1;
        }

        uint32_t ph[4][4], pl[4][4];
        #pragma unroll
        for (int nj = 0; nj < 4; nj++) {
            split2h(s[2*nj  ][0], s[2*nj  ][1], ph[nj][0], pl[nj][0]);
            split2h(s[2*nj  ][2], s[2*nj  ][3], ph[nj][1], pl[nj][1]);
            split2h(s[2*nj+1][0], s[2*nj+1][1], ph[nj][2], pl[nj][2]);
            split2h(s[2*nj+1][2], s[2*nj+1][3], ph[nj][3], pl[nj][3]);
        }

        #pragma unroll
        for (int nj = 0; nj < 4; nj++) {
            uint32_t bvh[8][2];
            #pragma unroll
            for (int ni = 0; ni < 8; ni++) {
                int bbase = (8*ni + g) * VP + 8*nj + qd;
                bvh[ni][0] = Vth[bbase]; bvh[ni][1] = Vth[bbase + 4];
            }
            #pragma unroll
            for (int ni = 0; ni < 8; ni++) mma16(o[ni], ph[nj], bvh[ni][0], bvh[ni][1]);
            #pragma unroll
            for (int ni = 0; ni < 8; ni++) mma16(o[ni], pl[nj], bvh[ni][0], bvh[ni][1]);
        }
    }

    float inv0 = 1.f / l0, inv1 = 1.f / l1;
    int b = bh >> 4, h = bh & 15;
    int n0 = q0 + mrow + g;
    #pragma unroll
    for (int ni = 0; ni < 8; ni++) {
        int col = h * HDIM + 8*ni + 2*qd;
        Out[((size_t)b * SEQ + n0) * DIM + col    ] = o[ni][0] * inv0;
        Out[((size_t)b * SEQ + n0) * DIM + col + 1] = o[ni][1] * inv0;
        Out[((size_t)b * SEQ + n0 + 8) * DIM + col    ] = o[ni][2] * inv1;
        Out[((size_t)b * SEQ + n0 + 8) * DIM + col + 1] = o[ni][3] * inv1;
    }
}

// ---------------- launch ----------------
extern "C" void kernel_launch(void* const* d_in, const int* in_sizes, int n_in,
                              void* d_out, int out_size)
{
    const float* z        = (const float*)d_in[0];
    const float* ln_scale = (const float*)d_in[1];
    const float* ln_bias  = (const float*)d_in[2];
    const float* w_qkv    = (const float*)d_in[3];
    const float* w_proj   = (const float*)d_in[4];
    const float* b_proj   = (const float*)d_in[5];
    float* out = (float*)d_out;

    float *zn, *att;
    cudaGetSymbolAddress((void**)&zn,  g_zn);
    cudaGetSymbolAddress((void**)&att, g_att);

    cudaFuncSetAttribute(gemm_fp16<0>, cudaFuncAttributeMaxDynamicSharedMemorySize, GEMM_SMEM_BYTES);
    cudaFuncSetAttribute(gemm_fp16<1>, cudaFuncAttributeMaxDynamicSharedMemorySize, GEMM_SMEM_BYTES);
    cudaFuncSetAttribute(attn_fp16,    cudaFuncAttributeMaxDynamicSharedMemorySize, ATTN_SMEM_BYTES);

    // 1) LayerNorm
    ln_kernel<<<ROWS, 256>>>(z, ln_scale, ln_bias, zn);

    // 2) QKV GEMM with de-interleave scatter epilogue
    gemm_fp16<0><<<dim3(QKVN / 128, ROWS / 128), 256, GEMM_SMEM_BYTES>>>(
        zn, w_qkv, nullptr, nullptr, nullptr, ROWS, QKVN, DIM);

    // 3) attention (fp16x2 flash, register-resident P)
    attn_fp16<<<dim3(SEQ / 128, BATCH * HEADS), 256, ATTN_SMEM_BYTES>>>(att);

    // 4) output projection + bias + residual
    gemm_fp16<1><<<dim3(DIM / 128, ROWS / 128), 256, GEMM_SMEM_BYTES>>>(
        att, w_proj, out, z, b_proj, ROWS, DIM, DIM);
}

// round 8
// speedup vs baseline: 3.2695x; 1.1132x over previous
#include <cuda_runtime.h>
#include <cuda_fp16.h>
#include <math.h>
#include <stdint.h>

#define BATCH 2
#define SEQ   2048
#define DIM   1024
#define HEADS 16
#define HDIM  64
#define ROWS  (BATCH * SEQ)      // 4096
#define QKVN  (3 * DIM)          // 3072
#define EPS   1e-5f
#define INV_SCALE 0.125f         // 1/sqrt(64)

// ---------------- scratch (__device__ globals) ----------------
__device__ uint32_t g_znh [ROWS * DIM / 2];   // LN out, fp16 hi (half2 along d)
__device__ uint32_t g_znl [ROWS * DIM / 2];   // LN out, fp16 lo residual
__device__ uint32_t g_wqkvT[QKVN * DIM / 2];  // w_qkv^T fp16 hi [3072][512]
__device__ uint32_t g_wprojT[DIM * DIM / 2];  // w_proj^T fp16 hi [1024][512]
__device__ float    g_q  [ROWS * DIM];        // Q fp32 [bh][n][d]
__device__ __half   g_kh [ROWS * DIM];        // K fp16 [bh][n][d]
__device__ __half   g_vth[ROWS * DIM];        // V fp16 TRANSPOSED [bh][d][n]
__device__ uint32_t g_atth[ROWS * DIM / 2];   // attn out fp16 hi (half2 along col)
__device__ uint32_t g_attl[ROWS * DIM / 2];   // attn out fp16 lo

// ---------------- helpers ----------------
__device__ __forceinline__ void split2h(float x, float y, uint32_t& h, uint32_t& l) {
    __half hx = __float2half_rn(x);
    __half hy = __float2half_rn(y);
    __half lx = __float2half_rn(x - __half2float(hx));
    __half ly = __float2half_rn(y - __half2float(hy));
    __half2 hh = __halves2half2(hx, hy);
    __half2 ll = __halves2half2(lx, ly);
    h = *reinterpret_cast<uint32_t*>(&hh);
    l = *reinterpret_cast<uint32_t*>(&ll);
}
__device__ __forceinline__ uint32_t pack2h(float x, float y) {
    __half2 hh = __halves2half2(__float2half_rn(x), __float2half_rn(y));
    return *reinterpret_cast<uint32_t*>(&hh);
}
__device__ __forceinline__ void mma16(float* c, const uint32_t* a, uint32_t b0, uint32_t b1) {
    asm volatile(
        "mma.sync.aligned.m16n8k16.row.col.f32.f16.f16.f32 "
        "{%0,%1,%2,%3}, {%4,%5,%6,%7}, {%8,%9}, {%0,%1,%2,%3};"
        : "+f"(c[0]), "+f"(c[1]), "+f"(c[2]), "+f"(c[3])
        : "r"(a[0]), "r"(a[1]), "r"(a[2]), "r"(a[3]), "r"(b0), "r"(b1));
}
__device__ __forceinline__ uint32_t smem_u32(const void* p) {
    return (uint32_t)__cvta_generic_to_shared(p);
}
#define CP16(dst, src) asm volatile("cp.async.cg.shared.global [%0], [%1], 16;" :: "r"(dst), "l"(src))
#define CP_COMMIT()    asm volatile("cp.async.commit_group;")
#define CP_WAIT1()     asm volatile("cp.async.wait_group 1;")
#define CP_WAIT0()     asm volatile("cp.async.wait_group 0;")

// ---------------- weight transpose+convert: W[K][N] fp32 -> WT[N][K/2] hi ----
__global__ __launch_bounds__(256) void convT(
    const float* __restrict__ W, uint32_t* __restrict__ WT, int N, int K)
{
    __shared__ float t[64][33];
    int n0 = blockIdx.x * 32, k0 = blockIdx.y * 64;
    int tid = threadIdx.x;
    #pragma unroll
    for (int i = 0; i < 8; i++) {
        int idx = tid + 256 * i;
        int r = idx >> 5, c = idx & 31;
        t[r][c] = W[(size_t)(k0 + r) * N + n0 + c];
    }
    __syncthreads();
    #pragma unroll
    for (int i = 0; i < 4; i++) {
        int idx = tid + 256 * i;
        int n = idx >> 5, kp = idx & 31;
        WT[(size_t)(n0 + n) * (K >> 1) + (k0 >> 1) + kp] =
            pack2h(t[2 * kp][n], t[2 * kp + 1][n]);
    }
}

// ---------------- LayerNorm -> packed fp16 hi/lo ----------------
__global__ __launch_bounds__(256) void ln_kernel(
    const float* __restrict__ z, const float* __restrict__ sc,
    const float* __restrict__ bi, uint32_t* __restrict__ oh,
    uint32_t* __restrict__ ol)
{
    int row = blockIdx.x;
    int t = threadIdx.x;
    const float4 v = ((const float4*)(z + row * DIM))[t];
    float s  = v.x + v.y + v.z + v.w;
    float s2 = v.x*v.x + v.y*v.y + v.z*v.z + v.w*v.w;

    __shared__ float ssum[8], ssum2[8], stats[2];
    #pragma unroll
    for (int off = 16; off > 0; off >>= 1) {
        s  += __shfl_down_sync(0xffffffffu, s,  off);
        s2 += __shfl_down_sync(0xffffffffu, s2, off);
    }
    int lane = t & 31, wid = t >> 5;
    if (lane == 0) { ssum[wid] = s; ssum2[wid] = s2; }
    __syncthreads();
    if (t == 0) {
        float a = 0.f, b = 0.f;
        #pragma unroll
        for (int i = 0; i < 8; i++) { a += ssum[i]; b += ssum2[i]; }
        float mu  = a * (1.0f / DIM);
        float var = b * (1.0f / DIM) - mu * mu;
        stats[0] = mu;
        stats[1] = rsqrtf(var + EPS);
    }
    __syncthreads();
    float mu = stats[0], rstd = stats[1];
    float4 s4 = ((const float4*)sc)[t];
    float4 b4 = ((const float4*)bi)[t];
    float rx = (v.x - mu) * rstd * s4.x + b4.x;
    float ry = (v.y - mu) * rstd * s4.y + b4.y;
    float rz = (v.z - mu) * rstd * s4.z + b4.z;
    float rw = (v.w - mu) * rstd * s4.w + b4.w;
    uint32_t h0, l0, h1, l1;
    split2h(rx, ry, h0, l0);
    split2h(rz, rw, h1, l1);
    oh[row * (DIM/2) + 2*t    ] = h0;
    ol[row * (DIM/2) + 2*t    ] = l0;
    oh[row * (DIM/2) + 2*t + 1] = h1;
    ol[row * (DIM/2) + 2*t + 1] = l1;
}

// ---------------- fp16x2 GEMM, cp.async pipelined ----------------
// A(hi/lo) packed [M][K/2]; BT packed [N][K/2]. 128x128 tile, k-step 32.
#define GP 20                               // row pad (uints), 80B (16B-aligned)
#define GSTAGE (3 * 128 * GP)               // uints per stage
#define GEMM_SMEM_BYTES (2 * GSTAGE * 4)    // 61440

template<int MODE>
__global__ __launch_bounds__(256, 2) void gemm_fp16(
    const uint32_t* __restrict__ Ah_g, const uint32_t* __restrict__ Al_g,
    const uint32_t* __restrict__ BT,
    float* __restrict__ C, const float* __restrict__ zres,
    const float* __restrict__ bias, int Ncols, int K)
{
    extern __shared__ uint32_t smg[];
    uint32_t sbase = smem_u32(smg);
    int tid = threadIdx.x;
    int wid = tid >> 5, lane = tid & 31;
    int wm = wid >> 2, wn = wid & 3;
    int g = lane >> 2, qd = lane & 3;
    int bm = blockIdx.y * 128, bn = blockIdx.x * 128;
    int Ku = K >> 1;

    auto issue = [&](int s, int c) {
        int kk2 = c * 16;
        uint32_t d0 = sbase + s * GSTAGE * 4;
        #pragma unroll
        for (int i = 0; i < 2; i++) {
            int ci = tid + 256 * i;
            int row = ci >> 2, off = (ci & 3) * 4;
            uint32_t d = d0 + (row * GP + off) * 4;
            CP16(d,                  Ah_g + (size_t)(bm + row) * Ku + kk2 + off);
            CP16(d + 128 * GP * 4,   Al_g + (size_t)(bm + row) * Ku + kk2 + off);
            CP16(d + 256 * GP * 4,   BT   + (size_t)(bn + row) * Ku + kk2 + off);
        }
        CP_COMMIT();
    };

    float acc[4][4][4] = {};

    issue(0, 0);
    int T = K / 32;
    for (int c = 0; c < T; c++) {
        int s = c & 1;
        if (c + 1 < T) { issue(s ^ 1, c + 1); CP_WAIT1(); }
        else           { CP_WAIT0(); }
        __syncthreads();

        uint32_t* Ah  = smg + s * GSTAGE;
        uint32_t* Al  = Ah + 128 * GP;
        uint32_t* Bth = Al + 128 * GP;

        #pragma unroll
        for (int chunk = 0; chunk < 2; chunk++) {
            int u0 = 8 * chunk;
            uint32_t ah[4][4], al_[4][4];
            #pragma unroll
            for (int mi = 0; mi < 4; mi++) {
                int base = (64*wm + 16*mi + g) * GP + u0 + qd;
                ah [mi][0] = Ah[base];          ah [mi][1] = Ah[base + 8*GP];
                ah [mi][2] = Ah[base + 4];      ah [mi][3] = Ah[base + 8*GP + 4];
                al_[mi][0] = Al[base];          al_[mi][1] = Al[base + 8*GP];
                al_[mi][2] = Al[base + 4];      al_[mi][3] = Al[base + 8*GP + 4];
            }
            uint32_t bh[4][2];
            #pragma unroll
            for (int ni = 0; ni < 4; ni++) {
                int base = (32*wn + 8*ni + g) * GP + u0 + qd;
                bh[ni][0] = Bth[base]; bh[ni][1] = Bth[base + 4];
            }
            #pragma unroll
            for (int mi = 0; mi < 4; mi++)
                #pragma unroll
                for (int ni = 0; ni < 4; ni++)
                    mma16(acc[mi][ni], ah[mi], bh[ni][0], bh[ni][1]);
            #pragma unroll
            for (int mi = 0; mi < 4; mi++)
                #pragma unroll
                for (int ni = 0; ni < 4; ni++)
                    mma16(acc[mi][ni], al_[mi], bh[ni][0], bh[ni][1]);
        }
        __syncthreads();
    }

    // epilogue
    #pragma unroll
    for (int mi = 0; mi < 4; mi++)
        #pragma unroll
        for (int ni = 0; ni < 4; ni++)
            #pragma unroll
            for (int j = 0; j < 4; j++) {
                int gm = bm + 64*wm + 16*mi + g + ((j >> 1) << 3);
                int gn = bn + 32*wn + 8*ni + 2*qd + (j & 1);
                float val = acc[mi][ni][j];
                if (MODE == 0) {
                    int bb = gm >> 11;
                    int nn = gm & (SEQ - 1);
                    int h   = gn / 192;
                    int rem = gn - h * 192;
                    int d   = rem / 3;
                    int w   = rem - d * 3;
                    int bh_ = bb * HEADS + h;
                    if (w == 0)
                        g_q[((size_t)bh_ * SEQ + nn) * HDIM + d] = val;
                    else if (w == 1)
                        g_kh[((size_t)bh_ * SEQ + nn) * HDIM + d] = __float2half_rn(val);
                    else
                        g_vth[((size_t)bh_ * HDIM + d) * SEQ + nn] = __float2half_rn(val);
                } else {
                    size_t idx = (size_t)gm * Ncols + gn;
                    C[idx] = val + bias[gn] + zres[idx];
                }
            }
}

// ---------------- fp16x2 flash attention, cp.async K/V, fp16 scratch --------
// 256 thr (8 warps), tile 128 q x 64 kv. Q fp32->split once; K/V fp16 direct.
#define QAP 36
#define KVP 36
#define KSTG (64 * KVP)                 // uints per K (or V) tile
#define ASTAGE (2 * KSTG)               // K+V per stage
#define ATTN_SMEM_BYTES ((2 * 128 * QAP + 2 * ASTAGE) * 4)   // 73728

__global__ __launch_bounds__(256, 2) void attn_fp16(
    uint32_t* __restrict__ Oh, uint32_t* __restrict__ Ol)
{
    extern __shared__ uint32_t sma[];
    uint32_t sbase = smem_u32(sma);
    uint32_t* Qh = sma;
    uint32_t* Ql = Qh + 128 * QAP;
    uint32_t* stg0 = Ql + 128 * QAP;    // stage s: K at s*ASTAGE, V at +KSTG

    int tid = threadIdx.x;
    int wid = tid >> 5, lane = tid & 31;
    int g = lane >> 2, qd = lane & 3;
    int bh = blockIdx.y;
    int q0 = blockIdx.x * 128;
    int mrow = wid * 16;

    const uint32_t* kh_u  = (const uint32_t*)g_kh;
    const uint32_t* vth_u = (const uint32_t*)g_vth;

    auto issue_kv = [&](int s, int kt) {
        uint32_t d0 = sbase + (2 * 128 * QAP + s * ASTAGE) * 4;
        #pragma unroll
        for (int i = 0; i < 2; i++) {
            int ci = tid + 256 * i;
            int row = ci >> 3, off = (ci & 7) * 4;
            uint32_t d = d0 + (row * KVP + off) * 4;
            CP16(d, kh_u + ((size_t)bh * SEQ + kt * 64 + row) * 32 + off);
            CP16(d + KSTG * 4, vth_u + ((size_t)bh * HDIM + row) * (SEQ/2) + kt * 32 + off);
        }
        CP_COMMIT();
    };

    issue_kv(0, 0);

    // load + split Q tile (fp32 -> hi/lo), overlaps first K/V fetch
    const float* Qb = g_q + ((size_t)bh * SEQ + q0) * HDIM;
    #pragma unroll
    for (int j = 0; j < 8; j++) {
        int idx = tid + 256 * j;
        int r = idx >> 4, c = (idx & 15) * 4;
        float4 v = *(const float4*)(Qb + r * 64 + c);
        int cb = c >> 1;
        uint32_t h, l;
        split2h(v.x, v.y, h, l); Qh[r*QAP+cb  ] = h; Ql[r*QAP+cb  ] = l;
        split2h(v.z, v.w, h, l); Qh[r*QAP+cb+1] = h; Ql[r*QAP+cb+1] = l;
    }

    float o[8][4] = {};
    float m0 = -1e30f, m1 = -1e30f, l0 = 0.f, l1 = 0.f;

    const int T = SEQ / 64;
    for (int kt = 0; kt < T; kt++) {
        int s = kt & 1;
        if (kt + 1 < T) { issue_kv(s ^ 1, kt + 1); CP_WAIT1(); }
        else            { CP_WAIT0(); }
        __syncthreads();

        uint32_t* Kh  = stg0 + s * ASTAGE;
        uint32_t* Vth = Kh + KSTG;

        // S = Q @ K^T (16 x 64 per warp), fp16x2
        float sS[8][4] = {};
        #pragma unroll
        for (int chunk = 0; chunk < 4; chunk++) {
            int u0 = 8 * chunk;
            uint32_t ah[4], al_[4];
            int abase = (mrow + g) * QAP + u0 + qd;
            ah [0] = Qh[abase];          ah [1] = Qh[abase + 8*QAP];
            ah [2] = Qh[abase + 4];      ah [3] = Qh[abase + 8*QAP + 4];
            al_[0] = Ql[abase];          al_[1] = Ql[abase + 8*QAP];
            al_[2] = Ql[abase + 4];      al_[3] = Ql[abase + 8*QAP + 4];
            uint32_t bh_[8][2];
            #pragma unroll
            for (int ni = 0; ni < 8; ni++) {
                int bbase = (8*ni + g) * KVP + u0 + qd;
                bh_[ni][0] = Kh[bbase]; bh_[ni][1] = Kh[bbase + 4];
            }
            #pragma unroll
            for (int ni = 0; ni < 8; ni++) mma16(sS[ni], ah,  bh_[ni][0], bh_[ni][1]);
            #pragma unroll
            for (int ni = 0; ni < 8; ni++) mma16(sS[ni], al_, bh_[ni][0], bh_[ni][1]);
        }
        #pragma unroll
        for (int ni = 0; ni < 8; ni++)
            #pragma unroll
            for (int j = 0; j < 4; j++) sS[ni][j] *= INV_SCALE;

        // online softmax (rows g and g+8)
        float t0 = -1e30f, t1 = -1e30f;
        #pragma unroll
        for (int ni = 0; ni < 8; ni++) {
            t0 = fmaxf(t0, fmaxf(sS[ni][0], sS[ni][1]));
            t1 = fmaxf(t1, fmaxf(sS[ni][2], sS[ni][3]));
        }
        t0 = fmaxf(t0, __shfl_xor_sync(0xffffffffu, t0, 1));
        t0 = fmaxf(t0, __shfl_xor_sync(0xffffffffu, t0, 2));
        t1 = fmaxf(t1, __shfl_xor_sync(0xffffffffu, t1, 1));
        t1 = fmaxf(t1, __shfl_xor_sync(0xffffffffu, t1, 2));
        float mn0 = fmaxf(m0, t0), mn1 = fmaxf(m1, t1);
        float a0 = __expf(m0 - mn0), a1 = __expf(m1 - mn1);
        m0 = mn0; m1 = mn1;
        float p0 = 0.f, p1 = 0.f;
        #pragma unroll
        for (int ni = 0; ni < 8; ni++) {
            sS[ni][0] = __expf(sS[ni][0] - mn0); p0 += sS[ni][0];
            sS[ni][1] = __expf(sS[ni][1] - mn0); p0 += sS[ni][1];
            sS[ni][2] = __expf(sS[ni][2] - mn1); p1 += sS[ni][2];
            sS[ni][3] = __expf(sS[ni][3] - mn1); p1 += sS[ni][3];
        }
        p0 += __shfl_xor_sync(0xffffffffu, p0, 1);
        p0 += __shfl_xor_sync(0xffffffffu, p0, 2);
        p1 += __shfl_xor_sync(0xffffffffu, p1, 1);
        p1 += __shfl_xor_sync(0xffffffffu, p1, 2);
        l0 = l0 * a0 + p0;
        l1 = l1 * a1 + p1;
        #pragma unroll
        for (int ni = 0; ni < 8; ni++) {
            o[ni][0] *= a0; o[ni][1] *= a0;
            o[ni][2] *= a1; o[ni][3] *= a1;
        }

        // P -> fp16 hi/lo A-fragments in registers
        uint32_t ph[4][4], pl[4][4];
        #pragma unroll
        for (int nj = 0; nj < 4; nj++) {
            split2h(sS[2*nj  ][0], sS[2*nj  ][1], ph[nj][0], pl[nj][0]);
            split2h(sS[2*nj  ][2], sS[2*nj  ][3], ph[nj][1], pl[nj][1]);
            split2h(sS[2*nj+1][0], sS[2*nj+1][1], ph[nj][2], pl[nj][2]);
            split2h(sS[2*nj+1][2], sS[2*nj+1][3], ph[nj][3], pl[nj][3]);
        }

        // O += P @ V
        #pragma unroll
        for (int nj = 0; nj < 4; nj++) {
            uint32_t bvh[8][2];
            #pragma unroll
            for (int ni = 0; ni < 8; ni++) {
                int bbase = (8*ni + g) * KVP + 8*nj + qd;
                bvh[ni][0] = Vth[bbase]; bvh[ni][1] = Vth[bbase + 4];
            }
            #pragma unroll
            for (int ni = 0; ni < 8; ni++) mma16(o[ni], ph[nj], bvh[ni][0], bvh[ni][1]);
            #pragma unroll
            for (int ni = 0; ni < 8; ni++) mma16(o[ni], pl[nj], bvh[ni][0], bvh[ni][1]);
        }
        __syncthreads();   // all reads of stage s done before it is refilled
    }

    // final: divide by l, split to fp16 hi/lo, packed write (cols adjacent)
    float inv0 = 1.f / l0, inv1 = 1.f / l1;
    int b = bh >> 4, h = bh & 15;
    int n0 = q0 + mrow + g;
    #pragma unroll
    for (int ni = 0; ni < 8; ni++) {
        int col = h * HDIM + 8*ni + 2*qd;
        uint32_t hh, ll;
        split2h(o[ni][0] * inv0, o[ni][1] * inv0, hh, ll);
        Oh[(((size_t)b * SEQ + n0) * DIM + col) >> 1] = hh;
        Ol[(((size_t)b * SEQ + n0) * DIM + col) >> 1] = ll;
        split2h(o[ni][2] * inv1, o[ni][3] * inv1, hh, ll);
        Oh[(((size_t)b * SEQ + n0 + 8) * DIM + col) >> 1] = hh;
        Ol[(((size_t)b * SEQ + n0 + 8) * DIM + col) >> 1] = ll;
    }
}

// ---------------- launch ----------------
extern "C" void kernel_launch(void* const* d_in, const int* in_sizes, int n_in,
                              void* d_out, int out_size)
{
    const float* z        = (const float*)d_in[0];
    const float* ln_scale = (const float*)d_in[1];
    const float* ln_bias  = (const float*)d_in[2];
    const float* w_qkv    = (const float*)d_in[3];
    const float* w_proj   = (const float*)d_in[4];
    const float* b_proj   = (const float*)d_in[5];
    float* out = (float*)d_out;

    uint32_t *znh, *znl, *wqkvT, *wprojT, *atth, *attl;
    cudaGetSymbolAddress((void**)&znh,   g_znh);
    cudaGetSymbolAddress((void**)&znl,   g_znl);
    cudaGetSymbolAddress((void**)&wqkvT, g_wqkvT);
    cudaGetSymbolAddress((void**)&wprojT,g_wprojT);
    cudaGetSymbolAddress((void**)&atth,  g_atth);
    cudaGetSymbolAddress((void**)&attl,  g_attl);

    cudaFuncSetAttribute(gemm_fp16<0>, cudaFuncAttributeMaxDynamicSharedMemorySize, GEMM_SMEM_BYTES);
    cudaFuncSetAttribute(gemm_fp16<1>, cudaFuncAttributeMaxDynamicSharedMemorySize, GEMM_SMEM_BYTES);
    cudaFuncSetAttribute(attn_fp16,    cudaFuncAttributeMaxDynamicSharedMemorySize, ATTN_SMEM_BYTES);

    // 0) weight transpose+convert (one-off per launch, ~8us)
    convT<<<dim3(QKVN / 32, DIM / 64), 256>>>(w_qkv,  wqkvT,  QKVN, DIM);
    convT<<<dim3(DIM  / 32, DIM / 64), 256>>>(w_proj, wprojT, DIM,  DIM);

    // 1) LayerNorm -> packed fp16 hi/lo
    ln_kernel<<<ROWS, 256>>>(z, ln_scale, ln_bias, znh, znl);

    // 2) QKV GEMM (cp.async pipelined) with fp16 k/v-transposed epilogue
    gemm_fp16<0><<<dim3(QKVN / 128, ROWS / 128), 256, GEMM_SMEM_BYTES>>>(
        znh, znl, wqkvT, nullptr, nullptr, nullptr, QKVN, DIM);

    // 3) attention (fp16x2 flash, cp.async K/V, fp16 hi/lo output)
    attn_fp16<<<dim3(SEQ / 128, BATCH * HEADS), 256, ATTN_SMEM_BYTES>>>(atth, attl);

    // 4) output projection + bias + residual
    gemm_fp16<1><<<dim3(DIM / 128, ROWS / 128), 256, GEMM_SMEM_BYTES>>>(
        atth, attl, wprojT, out, z, b_proj, DIM, DIM);
}

// round 9
// speedup vs baseline: 3.4491x; 1.0549x over previous
#include <cuda_runtime.h>
#include <cuda_fp16.h>
#include <math.h>
#include <stdint.h>

#define BATCH 2
#define SEQ   2048
#define DIM   1024
#define HEADS 16
#define HDIM  64
#define ROWS  (BATCH * SEQ)      // 4096
#define QKVN  (3 * DIM)          // 3072
#define EPS   1e-5f
#define INV_SCALE 0.125f         // 1/sqrt(64)

// ---------------- scratch (__device__ globals) ----------------
__device__ uint32_t g_znh [ROWS * DIM / 2];   // LN out, fp16 hi (half2 along d)
__device__ uint32_t g_znl [ROWS * DIM / 2];   // LN out, fp16 lo residual
__device__ uint32_t g_wqkvT[QKVN * DIM / 2];  // w_qkv^T fp16 hi [3072][512]
__device__ uint32_t g_wprojT[DIM * DIM / 2];  // w_proj^T fp16 hi [1024][512]
__device__ float    g_q  [ROWS * DIM];        // Q fp32 [bh][n][d]
__device__ __half   g_kh [ROWS * DIM];        // K fp16 [bh][n][d]
__device__ __half   g_vth[ROWS * DIM];        // V fp16 TRANSPOSED [bh][d][n]
__device__ uint32_t g_atth[ROWS * DIM / 2];   // attn out fp16 hi
__device__ uint32_t g_attl[ROWS * DIM / 2];   // attn out fp16 lo

// ---------------- helpers ----------------
__device__ __forceinline__ void split2h(float x, float y, uint32_t& h, uint32_t& l) {
    __half hx = __float2half_rn(x);
    __half hy = __float2half_rn(y);
    __half lx = __float2half_rn(x - __half2float(hx));
    __half ly = __float2half_rn(y - __half2float(hy));
    __half2 hh = __halves2half2(hx, hy);
    __half2 ll = __halves2half2(lx, ly);
    h = *reinterpret_cast<uint32_t*>(&hh);
    l = *reinterpret_cast<uint32_t*>(&ll);
}
__device__ __forceinline__ uint32_t pack2h(float x, float y) {
    __half2 hh = __halves2half2(__float2half_rn(x), __float2half_rn(y));
    return *reinterpret_cast<uint32_t*>(&hh);
}
__device__ __forceinline__ void mma16(float* c, const uint32_t* a, uint32_t b0, uint32_t b1) {
    asm volatile(
        "mma.sync.aligned.m16n8k16.row.col.f32.f16.f16.f32 "
        "{%0,%1,%2,%3}, {%4,%5,%6,%7}, {%8,%9}, {%0,%1,%2,%3};"
        : "+f"(c[0]), "+f"(c[1]), "+f"(c[2]), "+f"(c[3])
        : "r"(a[0]), "r"(a[1]), "r"(a[2]), "r"(a[3]), "r"(b0), "r"(b1));
}
__device__ __forceinline__ void ldsm4(uint32_t* r, uint32_t addr) {
    asm volatile("ldmatrix.sync.aligned.m8n8.x4.shared.b16 {%0,%1,%2,%3}, [%4];"
                 : "=r"(r[0]), "=r"(r[1]), "=r"(r[2]), "=r"(r[3]) : "r"(addr));
}
__device__ __forceinline__ uint32_t smem_u32(const void* p) {
    return (uint32_t)__cvta_generic_to_shared(p);
}
#define CP16(dst, src) asm volatile("cp.async.cg.shared.global [%0], [%1], 16;" :: "r"(dst), "l"(src))
#define CP_COMMIT()    asm volatile("cp.async.commit_group;")
#define CP_WAIT1()     asm volatile("cp.async.wait_group 1;")
#define CP_WAIT0()     asm volatile("cp.async.wait_group 0;")

// ---------------- weight transpose+convert: W[K][N] fp32 -> WT[N][K/2] hi ----
__global__ __launch_bounds__(256) void convT(
    const float* __restrict__ W, uint32_t* __restrict__ WT, int N, int K)
{
    __shared__ float t[64][33];
    int n0 = blockIdx.x * 32, k0 = blockIdx.y * 64;
    int tid = threadIdx.x;
    #pragma unroll
    for (int i = 0; i < 8; i++) {
        int idx = tid + 256 * i;
        int r = idx >> 5, c = idx & 31;
        t[r][c] = W[(size_t)(k0 + r) * N + n0 + c];
    }
    __syncthreads();
    #pragma unroll
    for (int i = 0; i < 4; i++) {
        int idx = tid + 256 * i;
        int n = idx >> 5, kp = idx & 31;
        WT[(size_t)(n0 + n) * (K >> 1) + (k0 >> 1) + kp] =
            pack2h(t[2 * kp][n], t[2 * kp + 1][n]);
    }
}

// ---------------- LayerNorm -> packed fp16 hi/lo ----------------
__global__ __launch_bounds__(256) void ln_kernel(
    const float* __restrict__ z, const float* __restrict__ sc,
    const float* __restrict__ bi, uint32_t* __restrict__ oh,
    uint32_t* __restrict__ ol)
{
    int row = blockIdx.x;
    int t = threadIdx.x;
    const float4 v = ((const float4*)(z + row * DIM))[t];
    float s  = v.x + v.y + v.z + v.w;
    float s2 = v.x*v.x + v.y*v.y + v.z*v.z + v.w*v.w;

    __shared__ float ssum[8], ssum2[8], stats[2];
    #pragma unroll
    for (int off = 16; off > 0; off >>= 1) {
        s  += __shfl_down_sync(0xffffffffu, s,  off);
        s2 += __shfl_down_sync(0xffffffffu, s2, off);
    }
    int lane = t & 31, wid = t >> 5;
    if (lane == 0) { ssum[wid] = s; ssum2[wid] = s2; }
    __syncthreads();
    if (t == 0) {
        float a = 0.f, b = 0.f;
        #pragma unroll
        for (int i = 0; i < 8; i++) { a += ssum[i]; b += ssum2[i]; }
        float mu  = a * (1.0f / DIM);
        float var = b * (1.0f / DIM) - mu * mu;
        stats[0] = mu;
        stats[1] = rsqrtf(var + EPS);
    }
    __syncthreads();
    float mu = stats[0], rstd = stats[1];
    float4 s4 = ((const float4*)sc)[t];
    float4 b4 = ((const float4*)bi)[t];
    float rx = (v.x - mu) * rstd * s4.x + b4.x;
    float ry = (v.y - mu) * rstd * s4.y + b4.y;
    float rz = (v.z - mu) * rstd * s4.z + b4.z;
    float rw = (v.w - mu) * rstd * s4.w + b4.w;
    uint32_t h0, l0, h1, l1;
    split2h(rx, ry, h0, l0);
    split2h(rz, rw, h1, l1);
    oh[row * (DIM/2) + 2*t    ] = h0;
    ol[row * (DIM/2) + 2*t    ] = l0;
    oh[row * (DIM/2) + 2*t + 1] = h1;
    ol[row * (DIM/2) + 2*t + 1] = l1;
}

// ---------------- fp16x2 GEMM, cp.async + ldmatrix ----------------
#define GP 20                               // row pad (uints), 80B
#define GSTAGE (3 * 128 * GP)
#define GEMM_SMEM_BYTES (2 * GSTAGE * 4)    // 61440

template<int MODE>
__global__ __launch_bounds__(256, 2) void gemm_fp16(
    const uint32_t* __restrict__ Ah_g, const uint32_t* __restrict__ Al_g,
    const uint32_t* __restrict__ BT,
    float* __restrict__ C, const float* __restrict__ zres,
    const float* __restrict__ bias, int Ncols, int K)
{
    extern __shared__ uint32_t smg[];
    uint32_t sbase = smem_u32(smg);
    int tid = threadIdx.x;
    int wid = tid >> 5, lane = tid & 31;
    int wm = wid >> 2, wn = wid & 3;
    int g = lane >> 2, qd = lane & 3;
    int bm = blockIdx.y * 128, bn = blockIdx.x * 128;
    int Ku = K >> 1;

    // ldmatrix per-lane address offsets
    int lm = lane & 7, seg = lane >> 3;
    int a_row = lm + 8 * (seg & 1), a_col = 4 * (seg >> 1);
    int b_row = lm + 8 * (seg >> 1), b_col = 4 * (seg & 1);
    uint32_t aoff[4], boff[2];
    #pragma unroll
    for (int mi = 0; mi < 4; mi++)
        aoff[mi] = ((64*wm + 16*mi + a_row) * GP + a_col) * 4;
    #pragma unroll
    for (int n2 = 0; n2 < 2; n2++)
        boff[n2] = ((32*wn + 16*n2 + b_row) * GP + b_col) * 4;

    auto issue = [&](int s, int c) {
        int kk2 = c * 16;
        uint32_t d0 = sbase + s * GSTAGE * 4;
        #pragma unroll
        for (int i = 0; i < 2; i++) {
            int ci = tid + 256 * i;
            int row = ci >> 2, off = (ci & 3) * 4;
            uint32_t d = d0 + (row * GP + off) * 4;
            CP16(d,                  Ah_g + (size_t)(bm + row) * Ku + kk2 + off);
            CP16(d + 128 * GP * 4,   Al_g + (size_t)(bm + row) * Ku + kk2 + off);
            CP16(d + 256 * GP * 4,   BT   + (size_t)(bn + row) * Ku + kk2 + off);
        }
        CP_COMMIT();
    };

    float acc[4][4][4] = {};

    issue(0, 0);
    int T = K / 32;
    for (int c = 0; c < T; c++) {
        int s = c & 1;
        if (c + 1 < T) { issue(s ^ 1, c + 1); CP_WAIT1(); }
        else           { CP_WAIT0(); }
        __syncthreads();

        uint32_t sA  = sbase + s * GSTAGE * 4;
        uint32_t sAl = sA + 128 * GP * 4;
        uint32_t sB  = sA + 256 * GP * 4;

        #pragma unroll
        for (int chunk = 0; chunk < 2; chunk++) {
            uint32_t u4 = chunk * 32;       // 8 uints = 32 bytes
            uint32_t ah[4][4], al_[4][4], bf[2][4];
            #pragma unroll
            for (int mi = 0; mi < 4; mi++) {
                ldsm4(ah[mi],  sA  + aoff[mi] + u4);
                ldsm4(al_[mi], sAl + aoff[mi] + u4);
            }
            #pragma unroll
            for (int n2 = 0; n2 < 2; n2++)
                ldsm4(bf[n2], sB + boff[n2] + u4);
            // bf[n2] = {b0(ni=2n2), b1(ni=2n2), b0(ni=2n2+1), b1(ni=2n2+1)}
            #pragma unroll
            for (int mi = 0; mi < 4; mi++)
                #pragma unroll
                for (int ni = 0; ni < 4; ni++)
                    mma16(acc[mi][ni], ah[mi], bf[ni>>1][(ni&1)*2], bf[ni>>1][(ni&1)*2+1]);
            #pragma unroll
            for (int mi = 0; mi < 4; mi++)
                #pragma unroll
                for (int ni = 0; ni < 4; ni++)
                    mma16(acc[mi][ni], al_[mi], bf[ni>>1][(ni&1)*2], bf[ni>>1][(ni&1)*2+1]);
        }
        __syncthreads();
    }

    // epilogue
    #pragma unroll
    for (int mi = 0; mi < 4; mi++)
        #pragma unroll
        for (int ni = 0; ni < 4; ni++)
            #pragma unroll
            for (int j = 0; j < 4; j++) {
                int gm = bm + 64*wm + 16*mi + g + ((j >> 1) << 3);
                int gn = bn + 32*wn + 8*ni + 2*qd + (j & 1);
                float val = acc[mi][ni][j];
                if (MODE == 0) {
                    int bb = gm >> 11;
                    int nn = gm & (SEQ - 1);
                    int h   = gn / 192;
                    int rem = gn - h * 192;
                    int d   = rem / 3;
                    int w   = rem - d * 3;
                    int bh_ = bb * HEADS + h;
                    if (w == 0)
                        g_q[((size_t)bh_ * SEQ + nn) * HDIM + d] = val;
                    else if (w == 1)
                        g_kh[((size_t)bh_ * SEQ + nn) * HDIM + d] = __float2half_rn(val);
                    else
                        g_vth[((size_t)bh_ * HDIM + d) * SEQ + nn] = __float2half_rn(val);
                } else {
                    size_t idx = (size_t)gm * Ncols + gn;
                    C[idx] = val + bias[gn] + zres[idx];
                }
            }
}

// ---------------- fp16x2 flash attention, cp.async + ldmatrix ---------------
#define QAP 36
#define KVP 36
#define KSTG (64 * KVP)
#define ASTAGE (2 * KSTG)
#define ATTN_SMEM_BYTES ((2 * 128 * QAP + 2 * ASTAGE) * 4)   // 73728

__global__ __launch_bounds__(256, 2) void attn_fp16(
    uint32_t* __restrict__ Oh, uint32_t* __restrict__ Ol)
{
    extern __shared__ uint32_t sma[];
    uint32_t sbase = smem_u32(sma);
    uint32_t* Qh = sma;
    uint32_t* Ql = Qh + 128 * QAP;

    int tid = threadIdx.x;
    int wid = tid >> 5, lane = tid & 31;
    int g = lane >> 2, qd = lane & 3;
    int bh = blockIdx.y;
    int q0 = blockIdx.x * 128;
    int mrow = wid * 16;

    // ldmatrix per-lane offsets
    int lm = lane & 7, seg = lane >> 3;
    int a_row = lm + 8 * (seg & 1), a_col = 4 * (seg >> 1);
    int b_row = lm + 8 * (seg >> 1), b_col = 4 * (seg & 1);
    uint32_t qoff = ((mrow + a_row) * QAP + a_col) * 4;
    uint32_t koff[4];
    #pragma unroll
    for (int n2 = 0; n2 < 4; n2++)
        koff[n2] = ((16*n2 + b_row) * KVP + b_col) * 4;

    uint32_t QhB = sbase;
    uint32_t QlB = sbase + 128 * QAP * 4;
    uint32_t St0 = sbase + 2 * 128 * QAP * 4;

    const uint32_t* kh_u  = (const uint32_t*)g_kh;
    const uint32_t* vth_u = (const uint32_t*)g_vth;

    auto issue_kv = [&](int s, int kt) {
        uint32_t d0 = St0 + s * ASTAGE * 4;
        #pragma unroll
        for (int i = 0; i < 2; i++) {
            int ci = tid + 256 * i;
            int row = ci >> 3, off = (ci & 7) * 4;
            uint32_t d = d0 + (row * KVP + off) * 4;
            CP16(d, kh_u + ((size_t)bh * SEQ + kt * 64 + row) * 32 + off);
            CP16(d + KSTG * 4, vth_u + ((size_t)bh * HDIM + row) * (SEQ/2) + kt * 32 + off);
        }
        CP_COMMIT();
    };

    issue_kv(0, 0);

    // load + split Q tile (fp32 -> hi/lo)
    const float* Qb = g_q + ((size_t)bh * SEQ + q0) * HDIM;
    #pragma unroll
    for (int j = 0; j < 8; j++) {
        int idx = tid + 256 * j;
        int r = idx >> 4, c = (idx & 15) * 4;
        float4 v = *(const float4*)(Qb + r * 64 + c);
        int cb = c >> 1;
        uint32_t h, l;
        split2h(v.x, v.y, h, l); Qh[r*QAP+cb  ] = h; Ql[r*QAP+cb  ] = l;
        split2h(v.z, v.w, h, l); Qh[r*QAP+cb+1] = h; Ql[r*QAP+cb+1] = l;
    }

    float o[8][4] = {};
    float m0 = -1e30f, m1 = -1e30f, l0 = 0.f, l1 = 0.f;

    const int T = SEQ / 64;
    for (int kt = 0; kt < T; kt++) {
        int s = kt & 1;
        if (kt + 1 < T) { issue_kv(s ^ 1, kt + 1); CP_WAIT1(); }
        else            { CP_WAIT0(); }
        __syncthreads();

        uint32_t KhB  = St0 + s * ASTAGE * 4;
        uint32_t VthB = KhB + KSTG * 4;

        // S = Q @ K^T (16 x 64 per warp)
        float sS[8][4] = {};
        #pragma unroll
        for (int chunk = 0; chunk < 4; chunk++) {
            uint32_t u4 = chunk * 32;
            uint32_t ah[4], al_[4], kf[4][4];
            ldsm4(ah,  QhB + qoff + u4);
            ldsm4(al_, QlB + qoff + u4);
            #pragma unroll
            for (int n2 = 0; n2 < 4; n2++)
                ldsm4(kf[n2], KhB + koff[n2] + u4);
            #pragma unroll
            for (int ni = 0; ni < 8; ni++)
                mma16(sS[ni], ah,  kf[ni>>1][(ni&1)*2], kf[ni>>1][(ni&1)*2+1]);
            #pragma unroll
            for (int ni = 0; ni < 8; ni++)
                mma16(sS[ni], al_, kf[ni>>1][(ni&1)*2], kf[ni>>1][(ni&1)*2+1]);
        }
        #pragma unroll
        for (int ni = 0; ni < 8; ni++)
            #pragma unroll
            for (int j = 0; j < 4; j++) sS[ni][j] *= INV_SCALE;

        // online softmax (rows g and g+8)
        float t0 = -1e30f, t1 = -1e30f;
        #pragma unroll
        for (int ni = 0; ni < 8; ni++) {
            t0 = fmaxf(t0, fmaxf(sS[ni][0], sS[ni][1]));
            t1 = fmaxf(t1, fmaxf(sS[ni][2], sS[ni][3]));
        }
        t0 = fmaxf(t0, __shfl_xor_sync(0xffffffffu, t0, 1));
        t0 = fmaxf(t0, __shfl_xor_sync(0xffffffffu, t0, 2));
        t1 = fmaxf(t1, __shfl_xor_sync(0xffffffffu, t1, 1));
        t1 = fmaxf(t1, __shfl_xor_sync(0xffffffffu, t1, 2));
        float mn0 = fmaxf(m0, t0), mn1 = fmaxf(m1, t1);
        float a0 = __expf(m0 - mn0), a1 = __expf(m1 - mn1);
        m0 = mn0; m1 = mn1;
        float p0 = 0.f, p1 = 0.f;
        #pragma unroll
        for (int ni = 0; ni < 8; ni++) {
            sS[ni][0] = __expf(sS[ni][0] - mn0); p0 += sS[ni][0];
            sS[ni][1] = __expf(sS[ni][1] - mn0); p0 += sS[ni][1];
            sS[ni][2] = __expf(sS[ni][2] - mn1); p1 += sS[ni][2];
            sS[ni][3] = __expf(sS[ni][3] - mn1); p1 += sS[ni][3];
        }
        p0 += __shfl_xor_sync(0xffffffffu, p0, 1);
        p0 += __shfl_xor_sync(0xffffffffu, p0, 2);
        p1 += __shfl_xor_sync(0xffffffffu, p1, 1);
        p1 += __shfl_xor_sync(0xffffffffu, p1, 2);
        l0 = l0 * a0 + p0;
        l1 = l1 * a1 + p1;
        #pragma unroll
        for (int ni = 0; ni < 8; ni++) {
            o[ni][0] *= a0; o[ni][1] *= a0;
            o[ni][2] *= a1; o[ni][3] *= a1;
        }

        // P -> fp16 hi/lo A-fragments in registers
        uint32_t ph[4][4], pl[4][4];
        #pragma unroll
        for (int nj = 0; nj < 4; nj++) {
            split2h(sS[2*nj  ][0], sS[2*nj  ][1], ph[nj][0], pl[nj][0]);
            split2h(sS[2*nj  ][2], sS[2*nj  ][3], ph[nj][1], pl[nj][1]);
            split2h(sS[2*nj+1][0], sS[2*nj+1][1], ph[nj][2], pl[nj][2]);
            split2h(sS[2*nj+1][2], sS[2*nj+1][3], ph[nj][3], pl[nj][3]);
        }

        // O += P @ V
        #pragma unroll
        for (int nj = 0; nj < 4; nj++) {
            uint32_t vf[4][4];
            #pragma unroll
            for (int n2 = 0; n2 < 4; n2++)
                ldsm4(vf[n2], VthB + koff[n2] + nj * 32);
            #pragma unroll
            for (int ni = 0; ni < 8; ni++)
                mma16(o[ni], ph[nj], vf[ni>>1][(ni&1)*2], vf[ni>>1][(ni&1)*2+1]);
            #pragma unroll
            for (int ni = 0; ni < 8; ni++)
                mma16(o[ni], pl[nj], vf[ni>>1][(ni&1)*2], vf[ni>>1][(ni&1)*2+1]);
        }
        __syncthreads();
    }

    // final: divide by l, split to fp16 hi/lo, packed write
    float inv0 = 1.f / l0, inv1 = 1.f / l1;
    int b = bh >> 4, h = bh & 15;
    int n0 = q0 + mrow + g;
    #pragma unroll
    for (int ni = 0; ni < 8; ni++) {
        int col = h * HDIM + 8*ni + 2*qd;
        uint32_t hh, ll;
        split2h(o[ni][0] * inv0, o[ni][1] * inv0, hh, ll);
        Oh[(((size_t)b * SEQ + n0) * DIM + col) >> 1] = hh;
        Ol[(((size_t)b * SEQ + n0) * DIM + col) >> 1] = ll;
        split2h(o[ni][2] * inv1, o[ni][3] * inv1, hh, ll);
        Oh[(((size_t)b * SEQ + n0 + 8) * DIM + col) >> 1] = hh;
        Ol[(((size_t)b * SEQ + n0 + 8) * DIM + col) >> 1] = ll;
    }
}

// ---------------- launch ----------------
extern "C" void kernel_launch(void* const* d_in, const int* in_sizes, int n_in,
                              void* d_out, int out_size)
{
    const float* z        = (const float*)d_in[0];
    const float* ln_scale = (const float*)d_in[1];
    const float* ln_bias  = (const float*)d_in[2];
    const float* w_qkv    = (const float*)d_in[3];
    const float* w_proj   = (const float*)d_in[4];
    const float* b_proj   = (const float*)d_in[5];
    float* out = (float*)d_out;

    uint32_t *znh, *znl, *wqkvT, *wprojT, *atth, *attl;
    cudaGetSymbolAddress((void**)&znh,   g_znh);
    cudaGetSymbolAddress((void**)&znl,   g_znl);
    cudaGetSymbolAddress((void**)&wqkvT, g_wqkvT);
    cudaGetSymbolAddress((void**)&wprojT,g_wprojT);
    cudaGetSymbolAddress((void**)&atth,  g_atth);
    cudaGetSymbolAddress((void**)&attl,  g_attl);

    cudaFuncSetAttribute(gemm_fp16<0>, cudaFuncAttributeMaxDynamicSharedMemorySize, GEMM_SMEM_BYTES);
    cudaFuncSetAttribute(gemm_fp16<1>, cudaFuncAttributeMaxDynamicSharedMemorySize, GEMM_SMEM_BYTES);
    cudaFuncSetAttribute(attn_fp16,    cudaFuncAttributeMaxDynamicSharedMemorySize, ATTN_SMEM_BYTES);

    // 0) weight transpose+convert (one-off per launch)
    convT<<<dim3(QKVN / 32, DIM / 64), 256>>>(w_qkv,  wqkvT,  QKVN, DIM);
    convT<<<dim3(DIM  / 32, DIM / 64), 256>>>(w_proj, wprojT, DIM,  DIM);

    // 1) LayerNorm -> packed fp16 hi/lo
    ln_kernel<<<ROWS, 256>>>(z, ln_scale, ln_bias, znh, znl);

    // 2) QKV GEMM (cp.async + ldmatrix) with fp16 k/v-transposed epilogue
    gemm_fp16<0><<<dim3(QKVN / 128, ROWS / 128), 256, GEMM_SMEM_BYTES>>>(
        znh, znl, wqkvT, nullptr, nullptr, nullptr, QKVN, DIM);

    // 3) attention (fp16x2 flash, cp.async + ldmatrix)
    attn_fp16<<<dim3(SEQ / 128, BATCH * HEADS), 256, ATTN_SMEM_BYTES>>>(atth, attl);

    // 4) output projection + bias + residual
    gemm_fp16<1><<<dim3(DIM / 128, ROWS / 128), 256, GEMM_SMEM_BYTES>>>(
        atth, attl, wprojT, out, z, b_proj, DIM, DIM);
}